// round 7
// baseline (speedup 1.0000x reference)
#include <cuda_runtime.h>
#include <math.h>

// Problem constants (fixed by the reference)
#define BB   128          // batch
#define TT   256          // timesteps
#define HH   1024         // hidden
#define CC   171          // frame size
#define NBLK 128          // persistent blocks (<= #SMs, co-resident guaranteed)
#define NTHR 256

#define SA_LD 33          // smem A row stride (pad: conflict-free)
#define SB_LD 33          // smem B row stride (pad: conflict-free)

// ---------------- persistent state (no allocations allowed) ----------------
__device__ float g_h[3][2][BB * HH];   // ping-pong hidden state per layer
__device__ float g_c[3][BB * HH];      // cell state (owner-exclusive, in-place)
__device__ unsigned long long g_arrive;   // monotonic ticket counter
__device__ unsigned long long g_release;  // last released ticket multiple

// ---------------- grid-wide barrier (monotonic, replay-safe) ---------------
__device__ __forceinline__ void grid_sync() {
    __threadfence();      // make this thread's global writes visible
    __syncthreads();
    if (threadIdx.x == 0) {
        unsigned long long a = atomicAdd(&g_arrive, 1ull) + 1ull;
        if ((a % (unsigned long long)NBLK) == 0ull) {
            __threadfence();
            *(volatile unsigned long long*)&g_release = a;
        } else {
            unsigned long long target =
                ((a + (unsigned long long)NBLK - 1ull) / (unsigned long long)NBLK)
                * (unsigned long long)NBLK;
            while (*(volatile unsigned long long*)&g_release < target) { }
            __threadfence();
        }
    }
    __syncthreads();
}

__device__ __forceinline__ float sigmf(float x) {
    return 1.0f / (1.0f + expf(-x));
}

// ---------------------------------------------------------------------------
// GEMM segment: acc[b_sub][gate] += A[b, k0:Ks] dot W[j, k0:Ks]
//   Block computes z for all 128 batch rows, 8 hidden units (u0..u0+7) x 4 gates.
//   smem column index col = uu*4 + gate  ->  W row j = gate*HH + u0 + uu
//   Thread map: uu = tid&7, rg = tid>>3; thread owns rows rg*4..rg*4+3, unit u0+uu.
// ---------------------------------------------------------------------------
__device__ __forceinline__ void gemm_seg(
    const float* __restrict__ A, int ldA, int Ks,
    const float* __restrict__ W, int ldW, int u0,
    float acc[4][4], float* sA, float* sB)
{
    const int t    = threadIdx.x;
    // A loader: 4 k-contiguous floats for 4 batch rows (coalesced 128B / 8 threads)
    const int la_k = (t & 7) * 4;
    const int la_b = t >> 3;
    // B loader: 4 k-contiguous floats of one W row
    const int lb_c    = t >> 3;          // smem column 0..31
    const int lb_k    = (t & 7) * 4;
    const int lb_gate = lb_c & 3;
    const int lb_uu   = lb_c >> 2;
    const float* Wrow = W + (long)(lb_gate * HH + u0 + lb_uu) * (long)ldW;
    // compute map
    const int rg = t >> 3;
    const int uu = t & 7;
    float* pA = sA + (rg * 4) * SA_LD;
    float* pB = sB + uu * 4;

    #pragma unroll 1
    for (int k0 = 0; k0 < Ks; k0 += 32) {
        // --- stage A tile [128 x 32] (zero-padded tail) ---
        #pragma unroll
        for (int i4 = 0; i4 < 4; i4++) {
            int b = la_b + 32 * i4;
            const float* Arow = A + (long)b * (long)ldA + k0 + la_k;
            #pragma unroll
            for (int j = 0; j < 4; j++) {
                int k = k0 + la_k + j;
                float v = (k < Ks) ? Arow[j] : 0.0f;
                sA[b * SA_LD + la_k + j] = v;
            }
        }
        // --- stage B tile [32 x 32] (zero-padded tail) ---
        #pragma unroll
        for (int j = 0; j < 4; j++) {
            int k = k0 + lb_k + j;
            float v = (k < Ks) ? Wrow[k] : 0.0f;
            sB[(lb_k + j) * SB_LD + lb_c] = v;
        }
        __syncthreads();
        // --- 4x4 register-tile FMA over 32 k ---
        #pragma unroll 8
        for (int kk = 0; kk < 32; kk++) {
            float a0 = pA[0 * SA_LD + kk];
            float a1 = pA[1 * SA_LD + kk];
            float a2 = pA[2 * SA_LD + kk];
            float a3 = pA[3 * SA_LD + kk];
            float b0 = pB[kk * SB_LD + 0];
            float b1 = pB[kk * SB_LD + 1];
            float b2 = pB[kk * SB_LD + 2];
            float b3 = pB[kk * SB_LD + 3];
            acc[0][0] += a0 * b0; acc[0][1] += a0 * b1; acc[0][2] += a0 * b2; acc[0][3] += a0 * b3;
            acc[1][0] += a1 * b0; acc[1][1] += a1 * b1; acc[1][2] += a1 * b2; acc[1][3] += a1 * b3;
            acc[2][0] += a2 * b0; acc[2][1] += a2 * b1; acc[2][2] += a2 * b2; acc[2][3] += a2 * b3;
            acc[3][0] += a3 * b0; acc[3][1] += a3 * b1; acc[3][2] += a3 * b2; acc[3][3] += a3 * b3;
        }
        __syncthreads();
    }
}

// LSTM gate activation + state update (thread-local: this thread owns (b, u))
__device__ __forceinline__ void lstm_epi(
    float acc[4][4],
    const float* __restrict__ bih, const float* __restrict__ bhh,
    float* __restrict__ c_st, float* __restrict__ h_out, int u0)
{
    const int t  = threadIdx.x;
    const int rg = t >> 3, uu = t & 7;
    const int u  = u0 + uu;
    const float b0 = bih[0 * HH + u] + bhh[0 * HH + u];  // i
    const float b1 = bih[1 * HH + u] + bhh[1 * HH + u];  // f
    const float b2 = bih[2 * HH + u] + bhh[2 * HH + u];  // g
    const float b3 = bih[3 * HH + u] + bhh[3 * HH + u];  // o
    #pragma unroll
    for (int i = 0; i < 4; i++) {
        int b = rg * 4 + i;
        float zi = acc[i][0] + b0;
        float zf = acc[i][1] + b1;
        float zg = acc[i][2] + b2;
        float zo = acc[i][3] + b3;
        float co = c_st[b * HH + u];
        float cn = sigmf(zf) * co + sigmf(zi) * tanhf(zg);
        float hn = sigmf(zo) * tanhf(cn);
        c_st[b * HH + u]  = cn;
        h_out[b * HH + u] = hn;
    }
}

// Decoder: out[b, t, c] = h3[b,:] . dec_w[c,:] + dec_b[c]
// 128 blocks = 16 batch-groups x 8 col-groups; 8 h3 rows staged in smem.
#define SH_LD 1036   // pad: 16B-aligned rows, conflict-free float4 reads
__device__ __forceinline__ void decoder_phase(
    const float* __restrict__ h3,
    const float* __restrict__ dw, const float* __restrict__ db,
    float* __restrict__ outt /* = out + t*CC */, float* sH)
{
    const int t   = threadIdx.x;
    const int bg  = blockIdx.x >> 3;
    const int cg  = blockIdx.x & 7;
    const int rb0 = bg * 8;
    const int cc0 = cg * 22;
    // stage 8 rows of h3 (coalesced)
    for (int e = t; e < 8 * HH; e += NTHR) {
        int r = e >> 10, k = e & (HH - 1);
        sH[r * SH_LD + k] = h3[(rb0 + r) * HH + k];
    }
    __syncthreads();
    if (t < 8 * 22) {
        int br = t / 22, cc = t % 22;
        int c  = cc0 + cc;
        if (c < CC) {
            const float4* wr = (const float4*)(dw + (long)c * HH);
            const float4* hr = (const float4*)(sH + br * SH_LD);
            float s = 0.0f;
            #pragma unroll 4
            for (int k4 = 0; k4 < HH / 4; k4++) {
                float4 w = wr[k4];
                float4 h = hr[k4];
                s += w.x * h.x + w.y * h.y + w.z * h.z + w.w * h.w;
            }
            outt[(long)(rb0 + br) * (long)(TT * CC) + c] = s + db[c];
        }
    }
    __syncthreads();
}

// ---------------------------------------------------------------------------
__global__ void __launch_bounds__(NTHR, 1) aclstm_kernel(
    const float* __restrict__ seq,
    const float* __restrict__ w_ih1, const float* __restrict__ w_hh1,
    const float* __restrict__ b_ih1, const float* __restrict__ b_hh1,
    const float* __restrict__ w_ih2, const float* __restrict__ w_hh2,
    const float* __restrict__ b_ih2, const float* __restrict__ b_hh2,
    const float* __restrict__ w_ih3, const float* __restrict__ w_hh3,
    const float* __restrict__ b_ih3, const float* __restrict__ b_hh3,
    const float* __restrict__ dec_w, const float* __restrict__ dec_b,
    const int* __restrict__ gtp, const int* __restrict__ condp,
    float* __restrict__ out)
{
    __shared__ __align__(16) float pool[8 * SH_LD];   // 33.2 KB, shared by GEMM & decoder
    float* sA = pool;
    float* sB = pool + BB * SA_LD;
    const int u0 = blockIdx.x * 8;

    // zero initial state (buffers read at t=0)
    for (int e = blockIdx.x * NTHR + threadIdx.x; e < BB * HH; e += NBLK * NTHR) {
        g_h[0][0][e] = 0.0f; g_h[1][0][e] = 0.0f; g_h[2][0][e] = 0.0f;
        g_c[0][e]    = 0.0f; g_c[1][e]    = 0.0f; g_c[2][e]    = 0.0f;
    }
    grid_sync();

    const int gt     = *gtp;
    const int cond   = *condp;
    int period = gt + cond;
    if (period < 1) period = 1;

    #pragma unroll 1
    for (int t = 0; t < TT; t++) {
        const int rd = t & 1, wr = rd ^ 1;
        const bool use_gt = (t % period) < gt;

        // ---- Layer 1 ----
        float acc[4][4];
        #pragma unroll
        for (int i = 0; i < 4; i++)
            #pragma unroll
            for (int g = 0; g < 4; g++) acc[i][g] = 0.0f;

        const float* A1 = use_gt ? (seq + (long)t * CC)
                                 : (t > 0 ? (out + (long)(t - 1) * CC) : (const float*)0);
        if (A1) gemm_seg(A1, TT * CC, CC, w_ih1, CC, u0, acc, sA, sB);
        gemm_seg(g_h[0][rd], HH, HH, w_hh1, HH, u0, acc, sA, sB);
        lstm_epi(acc, b_ih1, b_hh1, g_c[0], g_h[0][wr], u0);
        grid_sync();

        // ---- Layer 2 ----
        #pragma unroll
        for (int i = 0; i < 4; i++)
            #pragma unroll
            for (int g = 0; g < 4; g++) acc[i][g] = 0.0f;
        gemm_seg(g_h[0][wr], HH, HH, w_ih2, HH, u0, acc, sA, sB);
        gemm_seg(g_h[1][rd], HH, HH, w_hh2, HH, u0, acc, sA, sB);
        lstm_epi(acc, b_ih2, b_hh2, g_c[1], g_h[1][wr], u0);
        grid_sync();

        // ---- Layer 3 ----
        #pragma unroll
        for (int i = 0; i < 4; i++)
            #pragma unroll
            for (int g = 0; g < 4; g++) acc[i][g] = 0.0f;
        gemm_seg(g_h[1][wr], HH, HH, w_ih3, HH, u0, acc, sA, sB);
        gemm_seg(g_h[2][rd], HH, HH, w_hh3, HH, u0, acc, sA, sB);
        lstm_epi(acc, b_ih3, b_hh3, g_c[2], g_h[2][wr], u0);
        grid_sync();

        // ---- Decoder ----
        decoder_phase(g_h[2][wr], dec_w, dec_b, out + (long)t * CC, pool);
        grid_sync();   // out[t] visible before next step's self-feed
    }
}

// ---------------------------------------------------------------------------
extern "C" void kernel_launch(void* const* d_in, const int* in_sizes, int n_in,
                              void* d_out, int out_size)
{
    (void)in_sizes; (void)n_in; (void)out_size;
    aclstm_kernel<<<NBLK, NTHR>>>(
        (const float*)d_in[0],
        (const float*)d_in[1],  (const float*)d_in[2],
        (const float*)d_in[3],  (const float*)d_in[4],
        (const float*)d_in[5],  (const float*)d_in[6],
        (const float*)d_in[7],  (const float*)d_in[8],
        (const float*)d_in[9],  (const float*)d_in[10],
        (const float*)d_in[11], (const float*)d_in[12],
        (const float*)d_in[13], (const float*)d_in[14],
        (const int*)d_in[15],   (const int*)d_in[16],
        (float*)d_out);
}

// round 8
// speedup vs baseline: 1.5573x; 1.5573x over previous
#include <cuda_runtime.h>
#include <math.h>
#include <stdint.h>

// Problem constants (fixed by the reference)
#define BB   128          // batch
#define TT   256          // timesteps
#define HH   1024         // hidden
#define CC   171          // frame size
#define NBLK 128          // persistent blocks (<= #SMs, co-resident guaranteed)
#define NTHR 256

#define SA_LD 36          // smem A row stride (bank = 4g+t -> conflict-free frags)
#define SB_LD 36
#define SH_LD 1036        // decoder staging stride

// ---------------- persistent state (no allocations allowed) ----------------
__device__ float g_h[3][2][BB * HH];   // ping-pong hidden state per layer
__device__ float g_c[3][BB * HH];      // cell state (owner-exclusive, in-place)
__device__ unsigned long long g_arrive;   // monotonic ticket counter
__device__ unsigned long long g_release;  // last released ticket multiple

// ---------------- grid-wide barrier (monotonic, replay-safe) ---------------
__device__ __forceinline__ void grid_sync() {
    __threadfence();
    __syncthreads();
    if (threadIdx.x == 0) {
        unsigned long long a = atomicAdd(&g_arrive, 1ull) + 1ull;
        if ((a % (unsigned long long)NBLK) == 0ull) {
            __threadfence();
            *(volatile unsigned long long*)&g_release = a;
        } else {
            unsigned long long target =
                ((a + (unsigned long long)NBLK - 1ull) / (unsigned long long)NBLK)
                * (unsigned long long)NBLK;
            while (*(volatile unsigned long long*)&g_release < target) { }
            __threadfence();
        }
    }
    __syncthreads();
}

__device__ __forceinline__ float sigmf(float x) {
    return 1.0f / (1.0f + expf(-x));
}

// tf32 round-to-nearest (value kept in a b32 register)
__device__ __forceinline__ uint32_t f2tf32(float x) {
    uint32_t r;
    asm("cvt.rna.tf32.f32 %0, %1;" : "=r"(r) : "f"(x));
    return r;
}

// D += A(16x8,row) * B(8x8,col), tf32 inputs, f32 accum
__device__ __forceinline__ void mma8(float* d,
    uint32_t a0, uint32_t a1, uint32_t a2, uint32_t a3,
    uint32_t b0, uint32_t b1)
{
    asm volatile(
        "mma.sync.aligned.m16n8k8.row.col.f32.tf32.tf32.f32 "
        "{%0,%1,%2,%3}, {%4,%5,%6,%7}, {%8,%9}, {%0,%1,%2,%3};\n"
        : "+f"(d[0]), "+f"(d[1]), "+f"(d[2]), "+f"(d[3])
        : "r"(a0), "r"(a1), "r"(a2), "r"(a3), "r"(b0), "r"(b1));
}

// ---------------------------------------------------------------------------
// GEMM segment via tf32 split MMA.
//   Block tile: 128 batch rows x 32 cols. Col n -> gate = n>>3, unit = u0+(n&7).
//   Warp w owns rows 16w..16w+15 (one m-fragment), all 4 n-tiles of 8 cols.
//   acc[nt][0..3] = D-fragment of n-tile nt.
//   Full split: x = hi + lo (tf32); D += Ah*Bh + Al*Bh + Ah*Bl.
// VEC path requires: Ks % 32 == 0, ldA % 4 == 0, ldW % 4 == 0, 16B-aligned rows.
// ---------------------------------------------------------------------------
template <bool VEC>
__device__ __forceinline__ void gemm_mma(
    const float* __restrict__ A, long ldA, int Ks,
    const float* __restrict__ W, int ldW, int u0,
    float acc[4][4], float* __restrict__ sA, float* __restrict__ sB)
{
    const int t    = threadIdx.x;
    const int lane = t & 31;
    const int wrp  = t >> 5;
    const int g    = lane >> 2;
    const int tg   = lane & 3;
    const int row0 = wrp * 16;
    // A loader: rows la_r + 32i, 4 k-contiguous floats (coalesced)
    const int la_r = t >> 3;
    const int la_k = (t & 7) * 4;
    // B loader: one W row per smem n-row
    const int lb_n = t >> 3;
    const int lb_k = (t & 7) * 4;
    const float* Wrow =
        W + (long)((lb_n >> 3) * HH + u0 + (lb_n & 7)) * (long)ldW;

    float4 pa0, pa1, pa2, pa3, pb;
    if (VEC) {   // prefetch tile 0 into registers
        pa0 = *(const float4*)(A + (long)(la_r +  0) * ldA + la_k);
        pa1 = *(const float4*)(A + (long)(la_r + 32) * ldA + la_k);
        pa2 = *(const float4*)(A + (long)(la_r + 64) * ldA + la_k);
        pa3 = *(const float4*)(A + (long)(la_r + 96) * ldA + la_k);
        pb  = *(const float4*)(Wrow + lb_k);
    }

    #pragma unroll 1
    for (int k0 = 0; k0 < Ks; k0 += 32) {
        if (VEC) {
            *(float4*)(sA + (la_r +  0) * SA_LD + la_k) = pa0;
            *(float4*)(sA + (la_r + 32) * SA_LD + la_k) = pa1;
            *(float4*)(sA + (la_r + 64) * SA_LD + la_k) = pa2;
            *(float4*)(sA + (la_r + 96) * SA_LD + la_k) = pa3;
            *(float4*)(sB + lb_n * SB_LD + lb_k) = pb;
        } else {
            #pragma unroll
            for (int i = 0; i < 4; i++) {
                int r = la_r + 32 * i;
                const float* Ar = A + (long)r * ldA;
                #pragma unroll
                for (int j = 0; j < 4; j++) {
                    int k = k0 + la_k + j;
                    sA[r * SA_LD + la_k + j] = (k < Ks) ? Ar[k] : 0.0f;
                }
            }
            #pragma unroll
            for (int j = 0; j < 4; j++) {
                int k = k0 + lb_k + j;
                sB[lb_n * SB_LD + lb_k + j] = (k < Ks) ? Wrow[k] : 0.0f;
            }
        }
        __syncthreads();
        if (VEC && (k0 + 32 < Ks)) {   // prefetch next tile during compute
            const int kn = k0 + 32;
            pa0 = *(const float4*)(A + (long)(la_r +  0) * ldA + kn + la_k);
            pa1 = *(const float4*)(A + (long)(la_r + 32) * ldA + kn + la_k);
            pa2 = *(const float4*)(A + (long)(la_r + 64) * ldA + kn + la_k);
            pa3 = *(const float4*)(A + (long)(la_r + 96) * ldA + kn + la_k);
            pb  = *(const float4*)(Wrow + kn + lb_k);
        }
        #pragma unroll
        for (int m = 0; m < 4; m++) {
            const int kb = m * 8;
            // A fragment (raw), split in registers
            float ar0 = sA[(row0 + g    ) * SA_LD + kb + tg];
            float ar1 = sA[(row0 + g + 8) * SA_LD + kb + tg];
            float ar2 = sA[(row0 + g    ) * SA_LD + kb + tg + 4];
            float ar3 = sA[(row0 + g + 8) * SA_LD + kb + tg + 4];
            uint32_t ah0 = f2tf32(ar0), ah1 = f2tf32(ar1);
            uint32_t ah2 = f2tf32(ar2), ah3 = f2tf32(ar3);
            uint32_t al0 = __float_as_uint(ar0 - __uint_as_float(ah0));
            uint32_t al1 = __float_as_uint(ar1 - __uint_as_float(ah1));
            uint32_t al2 = __float_as_uint(ar2 - __uint_as_float(ah2));
            uint32_t al3 = __float_as_uint(ar3 - __uint_as_float(ah3));
            #pragma unroll
            for (int nt = 0; nt < 4; nt++) {
                float br0 = sB[(nt * 8 + g) * SB_LD + kb + tg];
                float br1 = sB[(nt * 8 + g) * SB_LD + kb + tg + 4];
                uint32_t bh0 = f2tf32(br0), bh1 = f2tf32(br1);
                uint32_t bl0 = __float_as_uint(br0 - __uint_as_float(bh0));
                uint32_t bl1 = __float_as_uint(br1 - __uint_as_float(bh1));
                mma8(acc[nt], ah0, ah1, ah2, ah3, bh0, bh1);
                mma8(acc[nt], al0, al1, al2, al3, bh0, bh1);
                mma8(acc[nt], ah0, ah1, ah2, ah3, bl0, bl1);
            }
        }
        __syncthreads();
    }
}

// LSTM epilogue: thread (w,g,t) owns rows {16w+g, 16w+g+8} x units {2t, 2t+1}
__device__ __forceinline__ void lstm_epi(
    float acc[4][4],
    const float* __restrict__ bih, const float* __restrict__ bhh,
    float* __restrict__ c_st, float* __restrict__ h_out, int u0)
{
    const int lane = threadIdx.x & 31;
    const int wrp  = threadIdx.x >> 5;
    const int g    = lane >> 2;
    const int tg   = lane & 3;
    #pragma unroll
    for (int half = 0; half < 2; half++) {
        const int b = wrp * 16 + g + half * 8;
        #pragma unroll
        for (int p = 0; p < 2; p++) {
            const int u   = u0 + 2 * tg + p;
            const int idx = half * 2 + p;
            float zi = acc[0][idx] + bih[0 * HH + u] + bhh[0 * HH + u];
            float zf = acc[1][idx] + bih[1 * HH + u] + bhh[1 * HH + u];
            float zg = acc[2][idx] + bih[2 * HH + u] + bhh[2 * HH + u];
            float zo = acc[3][idx] + bih[3 * HH + u] + bhh[3 * HH + u];
            float co = c_st[b * HH + u];
            float cn = sigmf(zf) * co + sigmf(zi) * tanhf(zg);
            float hn = sigmf(zo) * tanhf(cn);
            c_st[b * HH + u]  = cn;
            h_out[b * HH + u] = hn;
        }
    }
}

// Decoder: out[b, t, c] = h3[b,:] . dec_w[c,:] + dec_b[c]
__device__ __forceinline__ void decoder_phase(
    const float* __restrict__ h3,
    const float* __restrict__ dw, const float* __restrict__ db,
    float* __restrict__ outt, float* sH)
{
    const int t   = threadIdx.x;
    const int bg  = blockIdx.x >> 3;
    const int cg  = blockIdx.x & 7;
    const int rb0 = bg * 8;
    const int cc0 = cg * 22;
    for (int e = t; e < 8 * HH; e += NTHR) {
        int r = e >> 10, k = e & (HH - 1);
        sH[r * SH_LD + k] = h3[(rb0 + r) * HH + k];
    }
    __syncthreads();
    if (t < 8 * 22) {
        int br = t / 22, cc = t % 22;
        int c  = cc0 + cc;
        if (c < CC) {
            const float4* wr = (const float4*)(dw + (long)c * HH);
            const float4* hr = (const float4*)(sH + br * SH_LD);
            float s = 0.0f;
            #pragma unroll 4
            for (int k4 = 0; k4 < HH / 4; k4++) {
                float4 w = wr[k4];
                float4 h = hr[k4];
                s += w.x * h.x + w.y * h.y + w.z * h.z + w.w * h.w;
            }
            outt[(long)(rb0 + br) * (long)(TT * CC) + c] = s + db[c];
        }
    }
    __syncthreads();
}

// ---------------------------------------------------------------------------
__global__ void __launch_bounds__(NTHR, 1) aclstm_kernel(
    const float* __restrict__ seq,
    const float* __restrict__ w_ih1, const float* __restrict__ w_hh1,
    const float* __restrict__ b_ih1, const float* __restrict__ b_hh1,
    const float* __restrict__ w_ih2, const float* __restrict__ w_hh2,
    const float* __restrict__ b_ih2, const float* __restrict__ b_hh2,
    const float* __restrict__ w_ih3, const float* __restrict__ w_hh3,
    const float* __restrict__ b_ih3, const float* __restrict__ b_hh3,
    const float* __restrict__ dec_w, const float* __restrict__ dec_b,
    const int* __restrict__ gtp, const int* __restrict__ condp,
    float* __restrict__ out)
{
    // pool: GEMM needs 128*36 + 32*36 = 5760 floats; decoder needs 8*SH_LD.
    __shared__ __align__(16) float pool[8 * SH_LD];
    float* sA = pool;
    float* sB = pool + BB * SA_LD;
    const int u0 = blockIdx.x * 8;

    // zero initial state
    for (int e = blockIdx.x * NTHR + threadIdx.x; e < BB * HH; e += NBLK * NTHR) {
        g_h[0][0][e] = 0.0f; g_h[1][0][e] = 0.0f; g_h[2][0][e] = 0.0f;
        g_c[0][e]    = 0.0f; g_c[1][e]    = 0.0f; g_c[2][e]    = 0.0f;
    }
    grid_sync();

    const int gt   = *gtp;
    const int cond = *condp;
    int period = gt + cond;
    if (period < 1) period = 1;

    #pragma unroll 1
    for (int t = 0; t < TT; t++) {
        const int rd = t & 1, wr = rd ^ 1;
        const bool use_gt = (t % period) < gt;

        float acc[4][4];

        // ---- Layer 1 ----
        #pragma unroll
        for (int i = 0; i < 4; i++)
            #pragma unroll
            for (int j = 0; j < 4; j++) acc[i][j] = 0.0f;
        const float* A1 = use_gt ? (seq + (long)t * CC)
                                 : (t > 0 ? (out + (long)(t - 1) * CC)
                                          : (const float*)0);
        if (A1) gemm_mma<false>(A1, TT * CC, CC, w_ih1, CC, u0, acc, sA, sB);
        gemm_mma<true>(g_h[0][rd], HH, HH, w_hh1, HH, u0, acc, sA, sB);
        lstm_epi(acc, b_ih1, b_hh1, g_c[0], g_h[0][wr], u0);
        grid_sync();

        // ---- Layer 2 ----
        #pragma unroll
        for (int i = 0; i < 4; i++)
            #pragma unroll
            for (int j = 0; j < 4; j++) acc[i][j] = 0.0f;
        gemm_mma<true>(g_h[0][wr], HH, HH, w_ih2, HH, u0, acc, sA, sB);
        gemm_mma<true>(g_h[1][rd], HH, HH, w_hh2, HH, u0, acc, sA, sB);
        lstm_epi(acc, b_ih2, b_hh2, g_c[1], g_h[1][wr], u0);
        grid_sync();

        // ---- Layer 3 ----
        #pragma unroll
        for (int i = 0; i < 4; i++)
            #pragma unroll
            for (int j = 0; j < 4; j++) acc[i][j] = 0.0f;
        gemm_mma<true>(g_h[1][wr], HH, HH, w_ih3, HH, u0, acc, sA, sB);
        gemm_mma<true>(g_h[2][rd], HH, HH, w_hh3, HH, u0, acc, sA, sB);
        lstm_epi(acc, b_ih3, b_hh3, g_c[2], g_h[2][wr], u0);
        grid_sync();

        // ---- Decoder ----
        decoder_phase(g_h[2][wr], dec_w, dec_b, out + (long)t * CC, pool);
        grid_sync();   // out[t] visible before next step's self-feed
    }
}

// ---------------------------------------------------------------------------
extern "C" void kernel_launch(void* const* d_in, const int* in_sizes, int n_in,
                              void* d_out, int out_size)
{
    (void)in_sizes; (void)n_in; (void)out_size;
    aclstm_kernel<<<NBLK, NTHR>>>(
        (const float*)d_in[0],
        (const float*)d_in[1],  (const float*)d_in[2],
        (const float*)d_in[3],  (const float*)d_in[4],
        (const float*)d_in[5],  (const float*)d_in[6],
        (const float*)d_in[7],  (const float*)d_in[8],
        (const float*)d_in[9],  (const float*)d_in[10],
        (const float*)d_in[11], (const float*)d_in[12],
        (const float*)d_in[13], (const float*)d_in[14],
        (const int*)d_in[15],   (const int*)d_in[16],
        (float*)d_out);
}

// round 9
// speedup vs baseline: 2.0113x; 1.2916x over previous
#include <cuda_runtime.h>
#include <cuda_fp16.h>
#include <math.h>
#include <stdint.h>

#define BB   128
#define TT   256
#define HH   1024
#define CC   171
#define CCP  192          // padded frame width (multiple of 32)
#define NBLK 128
#define NTHR 256
#define SH_LD 1036        // decoder staging stride (floats)

// ---------------- persistent state (module statics, no runtime alloc) ------
__device__ __half g_hs[3][2][2][BB * HH];   // [layer][pingpong][split]
__device__ float  g_c[3][BB * HH];
__device__ float  g_h3[BB * HH];            // fp32 h3 for decoder
__device__ __half g_xs[2][BB * CCP];        // self-fed frame planes
__device__ __half g_seqs[2][TT * BB * CCP]; // pre-split seq planes [t][b][CCP]
__device__ unsigned long long g_arrive;
__device__ unsigned long long g_release;

// ---------------- grid-wide barrier (monotonic, replay-safe) ---------------
__device__ __forceinline__ void grid_sync() {
    __threadfence();
    __syncthreads();
    if (threadIdx.x == 0) {
        unsigned long long a = atomicAdd(&g_arrive, 1ull) + 1ull;
        if ((a % (unsigned long long)NBLK) == 0ull) {
            __threadfence();
            *(volatile unsigned long long*)&g_release = a;
        } else {
            unsigned long long target =
                ((a + (unsigned long long)NBLK - 1ull) / (unsigned long long)NBLK)
                * (unsigned long long)NBLK;
            while (*(volatile unsigned long long*)&g_release < target) { }
            __threadfence();
        }
    }
    __syncthreads();
}

__device__ __forceinline__ float sigmf(float x) {
    return 1.0f / (1.0f + expf(-x));
}

// D(16x8) += A(16x16,row) * B(16x8,col), fp16 in, fp32 accum
__device__ __forceinline__ void mma16(float* d,
    uint32_t a0, uint32_t a1, uint32_t a2, uint32_t a3,
    uint32_t b0, uint32_t b1)
{
    asm volatile(
        "mma.sync.aligned.m16n8k16.row.col.f32.f16.f16.f32 "
        "{%0,%1,%2,%3}, {%4,%5,%6,%7}, {%8,%9}, {%0,%1,%2,%3};\n"
        : "+f"(d[0]), "+f"(d[1]), "+f"(d[2]), "+f"(d[3])
        : "r"(a0), "r"(a1), "r"(a2), "r"(a3), "r"(b0), "r"(b1));
}

// Swizzled half-index within a 32-halfs (64B) row tile: chunk ^ ((r>>1)&3)
__device__ __forceinline__ int swz(int r, int chunk) {
    return r * 32 + ((chunk ^ ((r >> 1) & 3)) << 3);
}

__device__ __forceinline__ uint32_t pack2(float a, float b) {
    __half2 h = __halves2half2(__float2half_rn(a), __float2half_rn(b));
    return *(uint32_t*)&h;
}

// ---------------------------------------------------------------------------
// GEMM: block tile 128(batch) x 32(cols: gate=n>>3, unit=u0+(n&7)), fp16 2-split.
// A planes pre-split in gmem (half). W fp32, split on-the-fly in staging.
// accP += As0*Bs0 ; accQ += As1*Bs0 + As0*Bs1.
// TAIL: Ks not multiple of 32 (guarded scalar B loads, no prefetch).
// ---------------------------------------------------------------------------
template <bool TAIL>
__device__ __forceinline__ void gemm16(
    const __half* __restrict__ A0, const __half* __restrict__ A1,
    int ldA, int Ks,
    const float* __restrict__ W, int ldW, int u0,
    float (&accP)[4][4], float (&accQ)[4][4],
    __half* __restrict__ sA, __half* __restrict__ sB)
{
    const int t    = threadIdx.x;
    const int lane = t & 31;
    const int wrp  = t >> 5;
    const int g    = lane >> 2;
    const int tg   = lane & 3;
    const int row0 = wrp * 16;
    // A staging map: thread -> (row = ar+64i, chunk ac); gmem coalesced (uint4)
    const int ar = t >> 2;
    const int ac = t & 3;
    // B staging map: thread -> W row n (n = t>>3), 4 k-floats
    const int bn  = t >> 3;
    const int bk4 = (t & 7) * 4;
    const float* Wrow =
        W + (size_t)((bn >> 3) * HH + u0 + (bn & 7)) * (size_t)ldW;
    const int bidx = swz(bn, bk4 >> 3) + (bk4 & 7);

    __half* sA0 = sA;
    __half* sA1 = sA + BB * 32;
    __half* sB0 = sB;
    __half* sB1 = sB + 32 * 32;

    uint4 pa00, pa01, pa10, pa11;
    float4 pbv;
    if (!TAIL) {
        pa00 = *(const uint4*)(A0 + (size_t)(ar     ) * ldA + ac * 8);
        pa01 = *(const uint4*)(A0 + (size_t)(ar + 64) * ldA + ac * 8);
        pa10 = *(const uint4*)(A1 + (size_t)(ar     ) * ldA + ac * 8);
        pa11 = *(const uint4*)(A1 + (size_t)(ar + 64) * ldA + ac * 8);
        pbv  = *(const float4*)(Wrow + bk4);
    }

    #pragma unroll 1
    for (int k0 = 0; k0 < Ks; k0 += 32) {
        if (TAIL) {
            pa00 = *(const uint4*)(A0 + (size_t)(ar     ) * ldA + k0 + ac * 8);
            pa01 = *(const uint4*)(A0 + (size_t)(ar + 64) * ldA + k0 + ac * 8);
            pa10 = *(const uint4*)(A1 + (size_t)(ar     ) * ldA + k0 + ac * 8);
            pa11 = *(const uint4*)(A1 + (size_t)(ar + 64) * ldA + k0 + ac * 8);
            float f0, f1, f2, f3;
            int k = k0 + bk4;
            f0 = (k + 0 < Ks) ? Wrow[k + 0] : 0.0f;
            f1 = (k + 1 < Ks) ? Wrow[k + 1] : 0.0f;
            f2 = (k + 2 < Ks) ? Wrow[k + 2] : 0.0f;
            f3 = (k + 3 < Ks) ? Wrow[k + 3] : 0.0f;
            pbv = make_float4(f0, f1, f2, f3);
        }
        // ---- stage ----
        {
            int i0 = swz(ar, ac), i1 = swz(ar + 64, ac);
            *(uint4*)(sA0 + i0) = pa00;
            *(uint4*)(sA0 + i1) = pa01;
            *(uint4*)(sA1 + i0) = pa10;
            *(uint4*)(sA1 + i1) = pa11;
            // split W into hi/lo fp16
            float h0 = __half2float(__float2half_rn(pbv.x));
            float h1 = __half2float(__float2half_rn(pbv.y));
            float h2 = __half2float(__float2half_rn(pbv.z));
            float h3 = __half2float(__float2half_rn(pbv.w));
            uint2 vh = make_uint2(pack2(pbv.x, pbv.y), pack2(pbv.z, pbv.w));
            uint2 vl = make_uint2(pack2(pbv.x - h0, pbv.y - h1),
                                  pack2(pbv.z - h2, pbv.w - h3));
            *(uint2*)(sB0 + bidx) = vh;
            *(uint2*)(sB1 + bidx) = vl;
        }
        __syncthreads();
        if (!TAIL && (k0 + 32 < Ks)) {
            const int kn = k0 + 32;
            pa00 = *(const uint4*)(A0 + (size_t)(ar     ) * ldA + kn + ac * 8);
            pa01 = *(const uint4*)(A0 + (size_t)(ar + 64) * ldA + kn + ac * 8);
            pa10 = *(const uint4*)(A1 + (size_t)(ar     ) * ldA + kn + ac * 8);
            pa11 = *(const uint4*)(A1 + (size_t)(ar + 64) * ldA + kn + ac * 8);
            pbv  = *(const float4*)(Wrow + kn + bk4);
        }
        // ---- compute: 2 k-chunks of 16 ----
        #pragma unroll
        for (int kb = 0; kb < 2; kb++) {
            const int r0 = row0 + g, r1 = r0 + 8;
            const int c0 = 2 * kb, c1 = 2 * kb + 1;
            const int ia0 = swz(r0, c0) + 2 * tg;
            const int ia1 = swz(r1, c0) + 2 * tg;
            const int ia2 = swz(r0, c1) + 2 * tg;
            const int ia3 = swz(r1, c1) + 2 * tg;
            uint32_t ah0 = *(uint32_t*)(sA0 + ia0);
            uint32_t ah1 = *(uint32_t*)(sA0 + ia1);
            uint32_t ah2 = *(uint32_t*)(sA0 + ia2);
            uint32_t ah3 = *(uint32_t*)(sA0 + ia3);
            uint32_t al0 = *(uint32_t*)(sA1 + ia0);
            uint32_t al1 = *(uint32_t*)(sA1 + ia1);
            uint32_t al2 = *(uint32_t*)(sA1 + ia2);
            uint32_t al3 = *(uint32_t*)(sA1 + ia3);
            #pragma unroll
            for (int nt = 0; nt < 4; nt++) {
                const int n  = nt * 8 + g;
                const int ib0 = swz(n, c0) + 2 * tg;
                const int ib1 = swz(n, c1) + 2 * tg;
                uint32_t bh0 = *(uint32_t*)(sB0 + ib0);
                uint32_t bh1 = *(uint32_t*)(sB0 + ib1);
                uint32_t bl0 = *(uint32_t*)(sB1 + ib0);
                uint32_t bl1 = *(uint32_t*)(sB1 + ib1);
                mma16(accP[nt], ah0, ah1, ah2, ah3, bh0, bh1);
                mma16(accQ[nt], al0, al1, al2, al3, bh0, bh1);
                mma16(accQ[nt], ah0, ah1, ah2, ah3, bl0, bl1);
            }
        }
        __syncthreads();
    }
}

// LSTM epilogue: thread (w,g,t) owns rows {16w+g, 16w+g+8} x units {2t, 2t+1}.
// Writes fp16 split planes (+ optional fp32 h for decoder).
__device__ __forceinline__ void lstm_epi(
    float (&accP)[4][4], float (&accQ)[4][4],
    const float* __restrict__ bih, const float* __restrict__ bhh,
    float* __restrict__ c_st,
    __half* __restrict__ h0p, __half* __restrict__ h1p,
    float* __restrict__ hf, int u0)
{
    const int lane = threadIdx.x & 31;
    const int wrp  = threadIdx.x >> 5;
    const int g    = lane >> 2;
    const int tg   = lane & 3;
    #pragma unroll
    for (int half_ = 0; half_ < 2; half_++) {
        const int b = wrp * 16 + g + half_ * 8;
        float hn[2];
        #pragma unroll
        for (int p = 0; p < 2; p++) {
            const int u   = u0 + 2 * tg + p;
            const int idx = half_ * 2 + p;
            float zi = accP[0][idx] + accQ[0][idx] + bih[0 * HH + u] + bhh[0 * HH + u];
            float zf = accP[1][idx] + accQ[1][idx] + bih[1 * HH + u] + bhh[1 * HH + u];
            float zg = accP[2][idx] + accQ[2][idx] + bih[2 * HH + u] + bhh[2 * HH + u];
            float zo = accP[3][idx] + accQ[3][idx] + bih[3 * HH + u] + bhh[3 * HH + u];
            float co = c_st[b * HH + u];
            float cn = sigmf(zf) * co + sigmf(zi) * tanhf(zg);
            hn[p] = sigmf(zo) * tanhf(cn);
            c_st[b * HH + u] = cn;
            if (hf) hf[b * HH + u] = hn[p];
        }
        const int o = b * HH + u0 + 2 * tg;
        __half s00 = __float2half_rn(hn[0]);
        __half s01 = __float2half_rn(hn[1]);
        *(__half2*)(h0p + o) = __halves2half2(s00, s01);
        *(__half2*)(h1p + o) = __halves2half2(
            __float2half_rn(hn[0] - __half2float(s00)),
            __float2half_rn(hn[1] - __half2float(s01)));
    }
}

// Decoder: out[b,t,c] = h3[b,:].dec_w[c,:] + dec_b[c]; also writes split planes.
__device__ __forceinline__ void decoder_phase(
    const float* __restrict__ h3,
    const float* __restrict__ dw, const float* __restrict__ db,
    float* __restrict__ outt, float* sH)
{
    const int t   = threadIdx.x;
    const int bg  = blockIdx.x >> 3;
    const int cg  = blockIdx.x & 7;
    const int rb0 = bg * 8;
    const int cc0 = cg * 22;
    for (int e = t; e < 8 * HH; e += NTHR) {
        int r = e >> 10, k = e & (HH - 1);
        sH[r * SH_LD + k] = h3[(rb0 + r) * HH + k];
    }
    __syncthreads();
    if (t < 8 * 22) {
        int br = t / 22, cc = t % 22;
        int c  = cc0 + cc;
        if (c < CC) {
            const float4* wr = (const float4*)(dw + (size_t)c * HH);
            const float4* hr = (const float4*)(sH + br * SH_LD);
            float s = 0.0f;
            #pragma unroll 4
            for (int k4 = 0; k4 < HH / 4; k4++) {
                float4 w = wr[k4];
                float4 h = hr[k4];
                s += w.x * h.x + w.y * h.y + w.z * h.z + w.w * h.w;
            }
            float o = s + db[c];
            outt[(size_t)(rb0 + br) * (size_t)(TT * CC) + c] = o;
            __half s0 = __float2half_rn(o);
            g_xs[0][(rb0 + br) * CCP + c] = s0;
            g_xs[1][(rb0 + br) * CCP + c] =
                __float2half_rn(o - __half2float(s0));
        }
    }
    __syncthreads();
}

// ---------------------------------------------------------------------------
__global__ void __launch_bounds__(NTHR, 1) aclstm_kernel(
    const float* __restrict__ seq,
    const float* __restrict__ w_ih1, const float* __restrict__ w_hh1,
    const float* __restrict__ b_ih1, const float* __restrict__ b_hh1,
    const float* __restrict__ w_ih2, const float* __restrict__ w_hh2,
    const float* __restrict__ b_ih2, const float* __restrict__ b_hh2,
    const float* __restrict__ w_ih3, const float* __restrict__ w_hh3,
    const float* __restrict__ b_ih3, const float* __restrict__ b_hh3,
    const float* __restrict__ dec_w, const float* __restrict__ dec_b,
    const int* __restrict__ gtp, const int* __restrict__ condp,
    float* __restrict__ out)
{
    __shared__ __align__(16) float pool[8 * SH_LD];  // 33.2 KB, reused
    __half* sA = (__half*)pool;                       // 2 planes: 16 KB
    __half* sB = (__half*)pool + 2 * BB * 32;         // 2 planes: 4 KB
    const int u0 = blockIdx.x * 8;
    const int gtid = blockIdx.x * NTHR + threadIdx.x;
    const int gstr = NBLK * NTHR;

    // ---- init: zero state, zero x planes, pre-split seq planes ----
    for (int e = gtid; e < BB * HH; e += gstr) {
        #pragma unroll
        for (int l = 0; l < 3; l++) {
            g_hs[l][0][0][e] = __float2half_rn(0.0f);
            g_hs[l][0][1][e] = __float2half_rn(0.0f);
            g_c[l][e] = 0.0f;
        }
    }
    for (int e = gtid; e < BB * CCP; e += gstr) {
        g_xs[0][e] = __float2half_rn(0.0f);
        g_xs[1][e] = __float2half_rn(0.0f);
    }
    for (int n = gtid; n < TT * BB * CCP; n += gstr) {
        int tt = n / (BB * CCP);
        int r  = n - tt * (BB * CCP);
        int b  = r / CCP;
        int c  = r - b * CCP;
        float v = (c < CC) ? seq[((size_t)b * TT + tt) * CC + c] : 0.0f;
        __half s0 = __float2half_rn(v);
        g_seqs[0][n] = s0;
        g_seqs[1][n] = __float2half_rn(v - __half2float(s0));
    }
    grid_sync();

    const int gt   = *gtp;
    const int cond = *condp;
    int period = gt + cond;
    if (period < 1) period = 1;

    #pragma unroll 1
    for (int t = 0; t < TT; t++) {
        const int rd = t & 1, wr = rd ^ 1;
        const bool use_gt = (t % period) < gt;

        float accP[4][4], accQ[4][4];

        // ---- Layer 1 ----
        #pragma unroll
        for (int i = 0; i < 4; i++)
            #pragma unroll
            for (int j = 0; j < 4; j++) { accP[i][j] = 0.0f; accQ[i][j] = 0.0f; }
        const __half* X0 = use_gt ? (g_seqs[0] + (size_t)t * BB * CCP) : g_xs[0];
        const __half* X1 = use_gt ? (g_seqs[1] + (size_t)t * BB * CCP) : g_xs[1];
        gemm16<true >(X0, X1, CCP, CC, w_ih1, CC, u0, accP, accQ, sA, sB);
        gemm16<false>(g_hs[0][rd][0], g_hs[0][rd][1], HH, HH,
                      w_hh1, HH, u0, accP, accQ, sA, sB);
        lstm_epi(accP, accQ, b_ih1, b_hh1, g_c[0],
                 g_hs[0][wr][0], g_hs[0][wr][1], (float*)0, u0);
        grid_sync();

        // ---- Layer 2 ----
        #pragma unroll
        for (int i = 0; i < 4; i++)
            #pragma unroll
            for (int j = 0; j < 4; j++) { accP[i][j] = 0.0f; accQ[i][j] = 0.0f; }
        gemm16<false>(g_hs[0][wr][0], g_hs[0][wr][1], HH, HH,
                      w_ih2, HH, u0, accP, accQ, sA, sB);
        gemm16<false>(g_hs[1][rd][0], g_hs[1][rd][1], HH, HH,
                      w_hh2, HH, u0, accP, accQ, sA, sB);
        lstm_epi(accP, accQ, b_ih2, b_hh2, g_c[1],
                 g_hs[1][wr][0], g_hs[1][wr][1], (float*)0, u0);
        grid_sync();

        // ---- Layer 3 ----
        #pragma unroll
        for (int i = 0; i < 4; i++)
            #pragma unroll
            for (int j = 0; j < 4; j++) { accP[i][j] = 0.0f; accQ[i][j] = 0.0f; }
        gemm16<false>(g_hs[1][wr][0], g_hs[1][wr][1], HH, HH,
                      w_ih3, HH, u0, accP, accQ, sA, sB);
        gemm16<false>(g_hs[2][rd][0], g_hs[2][rd][1], HH, HH,
                      w_hh3, HH, u0, accP, accQ, sA, sB);
        lstm_epi(accP, accQ, b_ih3, b_hh3, g_c[2],
                 g_hs[2][wr][0], g_hs[2][wr][1], g_h3, u0);
        grid_sync();

        // ---- Decoder ----
        decoder_phase(g_h3, dec_w, dec_b, out + (size_t)t * CC, pool);
        grid_sync();   // out[t] + g_xs visible before next step
    }
}

// ---------------------------------------------------------------------------
extern "C" void kernel_launch(void* const* d_in, const int* in_sizes, int n_in,
                              void* d_out, int out_size)
{
    (void)in_sizes; (void)n_in; (void)out_size;
    aclstm_kernel<<<NBLK, NTHR>>>(
        (const float*)d_in[0],
        (const float*)d_in[1],  (const float*)d_in[2],
        (const float*)d_in[3],  (const float*)d_in[4],
        (const float*)d_in[5],  (const float*)d_in[6],
        (const float*)d_in[7],  (const float*)d_in[8],
        (const float*)d_in[9],  (const float*)d_in[10],
        (const float*)d_in[11], (const float*)d_in[12],
        (const float*)d_in[13], (const float*)d_in[14],
        (const int*)d_in[15],   (const int*)d_in[16],
        (float*)d_out);
}

// round 10
// speedup vs baseline: 2.1702x; 1.0790x over previous
#include <cuda_runtime.h>
#include <cuda_fp16.h>
#include <math.h>
#include <stdint.h>

#define BB   128
#define TT   256
#define HH   1024
#define CC   171
#define CCP  192          // padded frame width (3 x 64)
#define NBLK 128
#define NTHR 512
#define SH_LD 1036        // decoder staging stride (floats)

// smem buffer layout (in halves): per stage: A0|A1 (128x64 each) + B0|B1 (32x64)
#define A0_OFF 0
#define A1_OFF 8192
#define B0_OFF 16384
#define B1_OFF 18432
#define BUFH   20480
#define SMEM_BYTES (3 * BUFH * 2)   // 122880 B, 3-stage pipeline

// ---------------- persistent state (module statics, no runtime alloc) ------
__device__ __half g_hs[3][2][2][BB * HH];   // [layer][pingpong][split plane]
__device__ float  g_c[3][BB * HH];
__device__ float  g_h3[BB * HH];
__device__ __half g_xs[2][BB * CCP];        // self-fed frame planes
__device__ __half g_seqs[2][TT * BB * CCP]; // pre-split seq planes [t][b][CCP]
// pre-split weights (hi/lo fp16 planes), built at kernel start
__device__ __half g_w1i[2][4 * HH * CCP];
__device__ __half g_w1h[2][4 * HH * HH];
__device__ __half g_w2i[2][4 * HH * HH];
__device__ __half g_w2h[2][4 * HH * HH];
__device__ __half g_w3i[2][4 * HH * HH];
__device__ __half g_w3h[2][4 * HH * HH];
__device__ unsigned long long g_arrive;
__device__ unsigned long long g_release;

// ---------------- grid-wide barrier (monotonic, replay-safe) ---------------
__device__ __forceinline__ void grid_sync() {
    __threadfence();
    __syncthreads();
    if (threadIdx.x == 0) {
        unsigned long long a = atomicAdd(&g_arrive, 1ull) + 1ull;
        if ((a % (unsigned long long)NBLK) == 0ull) {
            __threadfence();
            *(volatile unsigned long long*)&g_release = a;
        } else {
            unsigned long long target =
                ((a + (unsigned long long)NBLK - 1ull) / (unsigned long long)NBLK)
                * (unsigned long long)NBLK;
            while (*(volatile unsigned long long*)&g_release < target) { }
            __threadfence();
        }
    }
    __syncthreads();
}

__device__ __forceinline__ float sigmf(float x) {
    return 1.0f / (1.0f + expf(-x));
}

// D(16x8) += A(16x16,row) * B(16x8,col), fp16 in, fp32 accum
__device__ __forceinline__ void mma16(float* d,
    uint32_t a0, uint32_t a1, uint32_t a2, uint32_t a3,
    uint32_t b0, uint32_t b1)
{
    asm volatile(
        "mma.sync.aligned.m16n8k16.row.col.f32.f16.f16.f32 "
        "{%0,%1,%2,%3}, {%4,%5,%6,%7}, {%8,%9}, {%0,%1,%2,%3};\n"
        : "+f"(d[0]), "+f"(d[1]), "+f"(d[2]), "+f"(d[3])
        : "r"(a0), "r"(a1), "r"(a2), "r"(a3), "r"(b0), "r"(b1));
}

__device__ __forceinline__ void cp16(void* dst_smem, const void* src) {
    uint32_t d = (uint32_t)__cvta_generic_to_shared(dst_smem);
    asm volatile("cp.async.cg.shared.global [%0], [%1], 16;"
                 :: "r"(d), "l"(src) : "memory");
}
#define CP_COMMIT() asm volatile("cp.async.commit_group;" ::: "memory")

// ---------------------------------------------------------------------------
// Stage one K=64 chunk into a smem buffer via cp.async (512 threads).
// Row layout: 64 halves (128B) per row, 8 chunks of 8 halves; phys chunk = c ^ (r&7).
// ---------------------------------------------------------------------------
__device__ __forceinline__ void stage_chunk(
    const __half* __restrict__ A0, const __half* __restrict__ A1, int ldA,
    const __half* __restrict__ W0, const __half* __restrict__ W1, int ldW,
    int u0, int k0, __half* __restrict__ buf)
{
    const int t = threadIdx.x;
    // A: thread -> row r = t>>2, chunks q and q+4, both planes (4 cp.asyncs)
    const int r = t >> 2, q = t & 3;
    const __half* s0 = A0 + (size_t)r * ldA + k0;
    const __half* s1 = A1 + (size_t)r * ldA + k0;
    __half* dA0 = buf + A0_OFF + r * 64;
    __half* dA1 = buf + A1_OFF + r * 64;
    const int p1 = ((q ^ (r & 7)) << 3);
    const int p2 = (((q + 4) ^ (r & 7)) << 3);
    cp16(dA0 + p1, s0 + q * 8);
    cp16(dA0 + p2, s0 + (q + 4) * 8);
    cp16(dA1 + p1, s1 + q * 8);
    cp16(dA1 + p2, s1 + (q + 4) * 8);
    // B: thread -> plane pl = t>>8, row n = (t>>3)&31, chunk c = t&7 (1 cp.async)
    const int pl = t >> 8, n = (t >> 3) & 31, c = t & 7;
    const __half* Wp = pl ? W1 : W0;
    const __half* sB =
        Wp + (size_t)((n >> 3) * HH + u0 + (n & 7)) * (size_t)ldW + k0 + c * 8;
    __half* dB = buf + (pl ? B1_OFF : B0_OFF) + n * 64 + ((c ^ (n & 7)) << 3);
    cp16(dB, sB);
}

// ---------------------------------------------------------------------------
// Compute one K=64 chunk. Warp wrp: wrow = wrp&7 -> rows 16*wrow..+15;
// khalf = wrp>>3 -> k sub-range [32*khalf, 32*khalf+32). 24 mma per warp.
// ---------------------------------------------------------------------------
__device__ __forceinline__ void compute_chunk(const __half* __restrict__ buf,
    float (&accP)[4][4], float (&accQ)[4][4])
{
    const int lane  = threadIdx.x & 31;
    const int wrp   = threadIdx.x >> 5;
    const int wrow  = wrp & 7;
    const int khalf = wrp >> 3;
    const int g  = lane >> 2;
    const int tg = lane & 3;
    const int r0 = wrow * 16 + g, r1 = r0 + 8;
    const __half* sA0 = buf + A0_OFF;
    const __half* sA1 = buf + A1_OFF;
    const __half* sB0 = buf + B0_OFF;
    const __half* sB1 = buf + B1_OFF;

    #pragma unroll
    for (int j = 0; j < 2; j++) {
        const int kb = khalf * 2 + j;
        const int o0 = (((2 * kb) ^ g) << 3) + 2 * tg;
        const int o1 = o0 ^ 8;
        uint32_t ah0 = *(const uint32_t*)(sA0 + r0 * 64 + o0);
        uint32_t ah1 = *(const uint32_t*)(sA0 + r1 * 64 + o0);
        uint32_t ah2 = *(const uint32_t*)(sA0 + r0 * 64 + o1);
        uint32_t ah3 = *(const uint32_t*)(sA0 + r1 * 64 + o1);
        uint32_t al0 = *(const uint32_t*)(sA1 + r0 * 64 + o0);
        uint32_t al1 = *(const uint32_t*)(sA1 + r1 * 64 + o0);
        uint32_t al2 = *(const uint32_t*)(sA1 + r0 * 64 + o1);
        uint32_t al3 = *(const uint32_t*)(sA1 + r1 * 64 + o1);
        #pragma unroll
        for (int nt = 0; nt < 4; nt++) {
            const int nr = (nt * 8 + g) * 64;
            uint32_t bh0 = *(const uint32_t*)(sB0 + nr + o0);
            uint32_t bh1 = *(const uint32_t*)(sB0 + nr + o1);
            uint32_t bl0 = *(const uint32_t*)(sB1 + nr + o0);
            uint32_t bl1 = *(const uint32_t*)(sB1 + nr + o1);
            mma16(accP[nt], ah0, ah1, ah2, ah3, bh0, bh1);
            mma16(accQ[nt], al0, al1, al2, al3, bh0, bh1);
            mma16(accQ[nt], ah0, ah1, ah2, ah3, bl0, bl1);
        }
    }
}

// ---------------------------------------------------------------------------
// Pipelined GEMM over nchunks K=64 chunks (3-stage, one __syncthreads/chunk)
// ---------------------------------------------------------------------------
__device__ __forceinline__ void gemm16(
    const __half* __restrict__ A0, const __half* __restrict__ A1,
    int ldA, int nchunks,
    const __half* __restrict__ W0, const __half* __restrict__ W1,
    int ldW, int u0,
    float (&accP)[4][4], float (&accQ)[4][4], __half* __restrict__ sm)
{
    __half* bufs[3] = { sm, sm + BUFH, sm + 2 * BUFH };
    __syncthreads();   // protect buffers from previous phase
    stage_chunk(A0, A1, ldA, W0, W1, ldW, u0, 0, bufs[0]);
    CP_COMMIT();
    if (nchunks > 1) {
        stage_chunk(A0, A1, ldA, W0, W1, ldW, u0, 64, bufs[1]);
        CP_COMMIT();
    }
    #pragma unroll 1
    for (int i = 0; i < nchunks; i++) {
        if (i + 1 < nchunks) {
            asm volatile("cp.async.wait_group 1;" ::: "memory");
        } else {
            asm volatile("cp.async.wait_group 0;" ::: "memory");
        }
        __syncthreads();
        if (i + 2 < nchunks) {
            stage_chunk(A0, A1, ldA, W0, W1, ldW, u0,
                        (i + 2) * 64, bufs[(i + 2) % 3]);
            CP_COMMIT();
        }
        compute_chunk(bufs[i % 3], accP, accQ);
    }
}

// ---------------------------------------------------------------------------
// Cross-khalf reduction + LSTM epilogue (warps 0-7 finish; rows as in R9).
// ---------------------------------------------------------------------------
__device__ __forceinline__ void layer_finish(
    float (&accP)[4][4], float (&accQ)[4][4],
    const float* __restrict__ bih, const float* __restrict__ bhh,
    float* __restrict__ c_st,
    __half* __restrict__ h0p, __half* __restrict__ h1p,
    float* __restrict__ hf, int u0, float* __restrict__ sred)
{
    const int lane = threadIdx.x & 31;
    const int wrp  = threadIdx.x >> 5;
    __syncthreads();   // all compute done; buffers reusable as sred
    if (wrp >= 8) {
        float* p = sred + ((wrp - 8) * 32 + lane) * 17;
        #pragma unroll
        for (int nt = 0; nt < 4; nt++)
            #pragma unroll
            for (int ii = 0; ii < 4; ii++)
                p[nt * 4 + ii] = accP[nt][ii] + accQ[nt][ii];
    }
    __syncthreads();
    if (wrp < 8) {
        const float* p = sred + (wrp * 32 + lane) * 17;
        float acc[4][4];
        #pragma unroll
        for (int nt = 0; nt < 4; nt++)
            #pragma unroll
            for (int ii = 0; ii < 4; ii++)
                acc[nt][ii] = accP[nt][ii] + accQ[nt][ii] + p[nt * 4 + ii];
        const int g  = lane >> 2;
        const int tg = lane & 3;
        #pragma unroll
        for (int half_ = 0; half_ < 2; half_++) {
            const int b = wrp * 16 + g + half_ * 8;
            float hn[2];
            #pragma unroll
            for (int pp = 0; pp < 2; pp++) {
                const int u   = u0 + 2 * tg + pp;
                const int idx = half_ * 2 + pp;
                float zi = acc[0][idx] + bih[0 * HH + u] + bhh[0 * HH + u];
                float zf = acc[1][idx] + bih[1 * HH + u] + bhh[1 * HH + u];
                float zg = acc[2][idx] + bih[2 * HH + u] + bhh[2 * HH + u];
                float zo = acc[3][idx] + bih[3 * HH + u] + bhh[3 * HH + u];
                float co = c_st[b * HH + u];
                float cn = sigmf(zf) * co + sigmf(zi) * tanhf(zg);
                hn[pp] = sigmf(zo) * tanhf(cn);
                c_st[b * HH + u] = cn;
                if (hf) hf[b * HH + u] = hn[pp];
            }
            const int o = b * HH + u0 + 2 * tg;
            __half s00 = __float2half_rn(hn[0]);
            __half s01 = __float2half_rn(hn[1]);
            *(__half2*)(h0p + o) = __halves2half2(s00, s01);
            *(__half2*)(h1p + o) = __halves2half2(
                __float2half_rn(hn[0] - __half2float(s00)),
                __float2half_rn(hn[1] - __half2float(s01)));
        }
    }
}

// Decoder: out[b,t,c] = h3[b,:].dec_w[c,:] + dec_b[c]; also writes x planes.
__device__ __forceinline__ void decoder_phase(
    const float* __restrict__ h3,
    const float* __restrict__ dw, const float* __restrict__ db,
    float* __restrict__ outt, float* __restrict__ sH)
{
    const int t   = threadIdx.x;
    const int bg  = blockIdx.x >> 3;
    const int cg  = blockIdx.x & 7;
    const int rb0 = bg * 8;
    const int cc0 = cg * 22;
    for (int e = t; e < 8 * HH; e += NTHR) {
        int r = e >> 10, k = e & (HH - 1);
        sH[r * SH_LD + k] = h3[(rb0 + r) * HH + k];
    }
    __syncthreads();
    if (t < 8 * 22) {
        int br = t / 22, cc = t % 22;
        int c  = cc0 + cc;
        if (c < CC) {
            const float4* wr = (const float4*)(dw + (size_t)c * HH);
            const float4* hr = (const float4*)(sH + br * SH_LD);
            float s = 0.0f;
            #pragma unroll 4
            for (int k4 = 0; k4 < HH / 4; k4++) {
                float4 w = wr[k4];
                float4 h = hr[k4];
                s += w.x * h.x + w.y * h.y + w.z * h.z + w.w * h.w;
            }
            float o = s + db[c];
            outt[(size_t)(rb0 + br) * (size_t)(TT * CC) + c] = o;
            __half s0 = __float2half_rn(o);
            g_xs[0][(rb0 + br) * CCP + c] = s0;
            g_xs[1][(rb0 + br) * CCP + c] =
                __float2half_rn(o - __half2float(s0));
        }
    }
    __syncthreads();
}

// Split one fp32 matrix [rows x lds] into padded fp16 hi/lo planes [rows x ldd]
__device__ __forceinline__ void split_mat(
    const float* __restrict__ src, __half* __restrict__ d0,
    __half* __restrict__ d1, int rows, int lds, int ldd, int gtid, int gstr)
{
    int total = rows * ldd;
    for (int n = gtid; n < total; n += gstr) {
        int r = n / ldd, c = n - r * ldd;
        float v = (c < lds) ? src[(size_t)r * lds + c] : 0.0f;
        __half h = __float2half_rn(v);
        d0[n] = h;
        d1[n] = __float2half_rn(v - __half2float(h));
    }
}

// ---------------------------------------------------------------------------
__global__ void __launch_bounds__(NTHR, 1) aclstm_kernel(
    const float* __restrict__ seq,
    const float* __restrict__ w_ih1, const float* __restrict__ w_hh1,
    const float* __restrict__ b_ih1, const float* __restrict__ b_hh1,
    const float* __restrict__ w_ih2, const float* __restrict__ w_hh2,
    const float* __restrict__ b_ih2, const float* __restrict__ b_hh2,
    const float* __restrict__ w_ih3, const float* __restrict__ w_hh3,
    const float* __restrict__ b_ih3, const float* __restrict__ b_hh3,
    const float* __restrict__ dec_w, const float* __restrict__ dec_b,
    const int* __restrict__ gtp, const int* __restrict__ condp,
    float* __restrict__ out)
{
    extern __shared__ __align__(16) unsigned char dynsm[];
    __half* sm   = (__half*)dynsm;
    float*  sred = (float*)dynsm;
    float*  sH   = (float*)dynsm;
    const int u0 = blockIdx.x * 8;
    const int gtid = blockIdx.x * NTHR + threadIdx.x;
    const int gstr = NBLK * NTHR;

    // ---- init: zero state & x planes, pre-split seq and all weights ----
    for (int e = gtid; e < BB * HH; e += gstr) {
        #pragma unroll
        for (int l = 0; l < 3; l++) {
            g_hs[l][0][0][e] = __float2half_rn(0.0f);
            g_hs[l][0][1][e] = __float2half_rn(0.0f);
            g_c[l][e] = 0.0f;
        }
    }
    for (int e = gtid; e < BB * CCP; e += gstr) {
        g_xs[0][e] = __float2half_rn(0.0f);
        g_xs[1][e] = __float2half_rn(0.0f);
    }
    for (int n = gtid; n < TT * BB * CCP; n += gstr) {
        int tt = n / (BB * CCP);
        int r  = n - tt * (BB * CCP);
        int b  = r / CCP;
        int c  = r - b * CCP;
        float v = (c < CC) ? seq[((size_t)b * TT + tt) * CC + c] : 0.0f;
        __half s0 = __float2half_rn(v);
        g_seqs[0][n] = s0;
        g_seqs[1][n] = __float2half_rn(v - __half2float(s0));
    }
    split_mat(w_ih1, g_w1i[0], g_w1i[1], 4 * HH, CC, CCP, gtid, gstr);
    split_mat(w_hh1, g_w1h[0], g_w1h[1], 4 * HH, HH, HH, gtid, gstr);
    split_mat(w_ih2, g_w2i[0], g_w2i[1], 4 * HH, HH, HH, gtid, gstr);
    split_mat(w_hh2, g_w2h[0], g_w2h[1], 4 * HH, HH, HH, gtid, gstr);
    split_mat(w_ih3, g_w3i[0], g_w3i[1], 4 * HH, HH, HH, gtid, gstr);
    split_mat(w_hh3, g_w3h[0], g_w3h[1], 4 * HH, HH, HH, gtid, gstr);
    grid_sync();

    const int gt   = *gtp;
    const int cond = *condp;
    int period = gt + cond;
    if (period < 1) period = 1;

    #pragma unroll 1
    for (int t = 0; t < TT; t++) {
        const int rd = t & 1, wr = rd ^ 1;
        const bool use_gt = (t % period) < gt;

        float accP[4][4], accQ[4][4];

        // ---- Layer 1 ----
        #pragma unroll
        for (int i = 0; i < 4; i++)
            #pragma unroll
            for (int j = 0; j < 4; j++) { accP[i][j] = 0.0f; accQ[i][j] = 0.0f; }
        const __half* X0 = use_gt ? (g_seqs[0] + (size_t)t * BB * CCP) : g_xs[0];
        const __half* X1 = use_gt ? (g_seqs[1] + (size_t)t * BB * CCP) : g_xs[1];
        gemm16(X0, X1, CCP, CCP / 64, g_w1i[0], g_w1i[1], CCP, u0,
               accP, accQ, sm);
        gemm16(g_hs[0][rd][0], g_hs[0][rd][1], HH, HH / 64,
               g_w1h[0], g_w1h[1], HH, u0, accP, accQ, sm);
        layer_finish(accP, accQ, b_ih1, b_hh1, g_c[0],
                     g_hs[0][wr][0], g_hs[0][wr][1], (float*)0, u0, sred);
        grid_sync();

        // ---- Layer 2 ----
        #pragma unroll
        for (int i = 0; i < 4; i++)
            #pragma unroll
            for (int j = 0; j < 4; j++) { accP[i][j] = 0.0f; accQ[i][j] = 0.0f; }
        gemm16(g_hs[0][wr][0], g_hs[0][wr][1], HH, HH / 64,
               g_w2i[0], g_w2i[1], HH, u0, accP, accQ, sm);
        gemm16(g_hs[1][rd][0], g_hs[1][rd][1], HH, HH / 64,
               g_w2h[0], g_w2h[1], HH, u0, accP, accQ, sm);
        layer_finish(accP, accQ, b_ih2, b_hh2, g_c[1],
                     g_hs[1][wr][0], g_hs[1][wr][1], (float*)0, u0, sred);
        grid_sync();

        // ---- Layer 3 ----
        #pragma unroll
        for (int i = 0; i < 4; i++)
            #pragma unroll
            for (int j = 0; j < 4; j++) { accP[i][j] = 0.0f; accQ[i][j] = 0.0f; }
        gemm16(g_hs[1][wr][0], g_hs[1][wr][1], HH, HH / 64,
               g_w3i[0], g_w3i[1], HH, u0, accP, accQ, sm);
        gemm16(g_hs[2][rd][0], g_hs[2][rd][1], HH, HH / 64,
               g_w3h[0], g_w3h[1], HH, u0, accP, accQ, sm);
        layer_finish(accP, accQ, b_ih3, b_hh3, g_c[2],
                     g_hs[2][wr][0], g_hs[2][wr][1], g_h3, u0, sred);
        grid_sync();

        // ---- Decoder ----
        __syncthreads();
        decoder_phase(g_h3, dec_w, dec_b, out + (size_t)t * CC, sH);
        grid_sync();   // out[t] + g_xs visible before next step
    }
}

// ---------------------------------------------------------------------------
extern "C" void kernel_launch(void* const* d_in, const int* in_sizes, int n_in,
                              void* d_out, int out_size)
{
    (void)in_sizes; (void)n_in; (void)out_size;
    cudaFuncSetAttribute(aclstm_kernel,
                         cudaFuncAttributeMaxDynamicSharedMemorySize,
                         SMEM_BYTES);
    aclstm_kernel<<<NBLK, NTHR, SMEM_BYTES>>>(
        (const float*)d_in[0],
        (const float*)d_in[1],  (const float*)d_in[2],
        (const float*)d_in[3],  (const float*)d_in[4],
        (const float*)d_in[5],  (const float*)d_in[6],
        (const float*)d_in[7],  (const float*)d_in[8],
        (const float*)d_in[9],  (const float*)d_in[10],
        (const float*)d_in[11], (const float*)d_in[12],
        (const float*)d_in[13], (const float*)d_in[14],
        (const int*)d_in[15],   (const int*)d_in[16],
        (float*)d_out);
}

// round 11
// speedup vs baseline: 2.9359x; 1.3529x over previous
#include <cuda_runtime.h>
#include <cuda_fp16.h>
#include <math.h>
#include <stdint.h>

#define BB   128
#define TT   256
#define HH   1024
#define CC   171
#define NBLK 128
#define NTHR 512
#define SH_LD 1036

// smem stage layout (halves): A0|A1 (128x64 each) | B0|B1 (32x64 each)
#define A0_OFF 0
#define A1_OFF 8192
#define B0_OFF 16384
#define B1_OFF 18432
#define BUFH   20480
#define STAGE_BYTES 40960
#define MB_OFF (3 * STAGE_BYTES)          // mbarriers after the 3 stage buffers
#define SMEM_BYTES (MB_OFF + 64)

#define HCH  16384            // halves per A chunk (2 planes x 128 x 64)
#define HLAY (16 * HCH)       // halves per h plane-set (16 chunks)
#define WCH  4096             // halves per W chunk (2 planes x 32 x 64)

// ---------------- persistent state (module statics, no runtime alloc) ------
__device__ __align__(16) __half g_hA[3][2][HLAY];      // pre-swizzled h chunks
__device__ __align__(16) __half g_xA[3 * HCH];         // self-fed frame chunks
__device__ __align__(16) __half g_seqA[TT][3 * HCH];   // pre-split seq chunks
__device__ __align__(16) __half g_wb[5][NBLK][16 * WCH]; // big weights per block
__device__ __align__(16) __half g_w1b[NBLK][3 * WCH];    // w_ih1 per block
__device__ float g_c[3][BB * HH];
__device__ float g_h3[BB * HH];
__device__ unsigned long long g_arrive;
__device__ unsigned long long g_release;

// ---------------- grid-wide barrier (monotonic, replay-safe) ---------------
__device__ __forceinline__ void grid_sync() {
    __threadfence();
    __syncthreads();
    if (threadIdx.x == 0) {
        unsigned long long a = atomicAdd(&g_arrive, 1ull) + 1ull;
        if ((a % (unsigned long long)NBLK) == 0ull) {
            __threadfence();
            *(volatile unsigned long long*)&g_release = a;
        } else {
            unsigned long long target =
                ((a + (unsigned long long)NBLK - 1ull) / (unsigned long long)NBLK)
                * (unsigned long long)NBLK;
            while (*(volatile unsigned long long*)&g_release < target) { }
            __threadfence();
        }
    }
    __syncthreads();
}

__device__ __forceinline__ float sigmf(float x) {
    return 1.0f / (1.0f + expf(-x));
}

// ---------------- mbarrier helpers -----------------------------------------
__device__ __forceinline__ void mbar_init(uint32_t mbar, uint32_t count) {
    asm volatile("mbarrier.init.shared.b64 [%0], %1;"
                 :: "r"(mbar), "r"(count) : "memory");
}
__device__ __forceinline__ void mbar_arrive(uint32_t mbar) {
    asm volatile("mbarrier.arrive.shared.b64 _, [%0];"
                 :: "r"(mbar) : "memory");
}
__device__ __forceinline__ void mbar_expect(uint32_t mbar, uint32_t tx) {
    asm volatile("mbarrier.arrive.expect_tx.shared.b64 _, [%0], %1;"
                 :: "r"(mbar), "r"(tx) : "memory");
}
__device__ __forceinline__ void mbar_wait(uint32_t mbar, uint32_t parity) {
    asm volatile(
        "{\n\t.reg .pred P;\n\t"
        "WL%=:\n\t"
        "mbarrier.try_wait.parity.shared::cta.b64 P, [%0], %1;\n\t"
        "@!P bra WL%=;\n\t}"
        :: "r"(mbar), "r"(parity) : "memory");
}
__device__ __forceinline__ void bulkcp(uint32_t dst, const void* src,
                                       uint32_t bytes, uint32_t mbar) {
    asm volatile(
        "cp.async.bulk.shared::cluster.global.mbarrier::complete_tx::bytes "
        "[%0], [%1], %2, [%3];"
        :: "r"(dst), "l"(src), "r"(bytes), "r"(mbar) : "memory");
}

// D(16x8) += A(16x16,row) * B(16x8,col), fp16 in, fp32 accum
__device__ __forceinline__ void mma16(float* d,
    uint32_t a0, uint32_t a1, uint32_t a2, uint32_t a3,
    uint32_t b0, uint32_t b1)
{
    asm volatile(
        "mma.sync.aligned.m16n8k16.row.col.f32.f16.f16.f32 "
        "{%0,%1,%2,%3}, {%4,%5,%6,%7}, {%8,%9}, {%0,%1,%2,%3};\n"
        : "+f"(d[0]), "+f"(d[1]), "+f"(d[2]), "+f"(d[3])
        : "r"(a0), "r"(a1), "r"(a2), "r"(a3), "r"(b0), "r"(b1));
}

// ---------------------------------------------------------------------------
// Compute one K=64 chunk. Warp wrp: wrow = wrp&7 -> rows 16*wrow..+15;
// khalf = wrp>>3 -> k sub-range. Swizzle: phys chunk8 = q ^ (row&7).
// ---------------------------------------------------------------------------
__device__ __forceinline__ void compute_chunk(const __half* __restrict__ buf,
    float (&accP)[4][4], float (&accQ)[4][4])
{
    const int lane  = threadIdx.x & 31;
    const int wrp   = threadIdx.x >> 5;
    const int wrow  = wrp & 7;
    const int khalf = wrp >> 3;
    const int g  = lane >> 2;
    const int tg = lane & 3;
    const int r0 = wrow * 16 + g, r1 = r0 + 8;
    const __half* sA0 = buf + A0_OFF;
    const __half* sA1 = buf + A1_OFF;
    const __half* sB0 = buf + B0_OFF;
    const __half* sB1 = buf + B1_OFF;

    #pragma unroll
    for (int j = 0; j < 2; j++) {
        const int kb = khalf * 2 + j;
        const int o0 = (((2 * kb) ^ g) << 3) + 2 * tg;
        const int o1 = o0 ^ 8;
        uint32_t ah0 = *(const uint32_t*)(sA0 + r0 * 64 + o0);
        uint32_t ah1 = *(const uint32_t*)(sA0 + r1 * 64 + o0);
        uint32_t ah2 = *(const uint32_t*)(sA0 + r0 * 64 + o1);
        uint32_t ah3 = *(const uint32_t*)(sA0 + r1 * 64 + o1);
        uint32_t al0 = *(const uint32_t*)(sA1 + r0 * 64 + o0);
        uint32_t al1 = *(const uint32_t*)(sA1 + r1 * 64 + o0);
        uint32_t al2 = *(const uint32_t*)(sA1 + r0 * 64 + o1);
        uint32_t al3 = *(const uint32_t*)(sA1 + r1 * 64 + o1);
        #pragma unroll
        for (int nt = 0; nt < 4; nt++) {
            const int nr = (nt * 8 + g) * 64;
            uint32_t bh0 = *(const uint32_t*)(sB0 + nr + o0);
            uint32_t bh1 = *(const uint32_t*)(sB0 + nr + o1);
            uint32_t bl0 = *(const uint32_t*)(sB1 + nr + o0);
            uint32_t bl1 = *(const uint32_t*)(sB1 + nr + o1);
            mma16(accP[nt], ah0, ah1, ah2, ah3, bh0, bh1);
            mma16(accQ[nt], al0, al1, al2, al3, bh0, bh1);
            mma16(accQ[nt], ah0, ah1, ah2, ah3, bl0, bl1);
        }
    }
}

// ---------------------------------------------------------------------------
// Bulk-copy pipelined GEMM over nchunks K=64 chunks (3-slot mbarrier ring).
// gidx: monotonically increasing global chunk counter (same in all threads).
// ---------------------------------------------------------------------------
__device__ __forceinline__ void gemm16(
    const __half* __restrict__ Asrc, const __half* __restrict__ Wsrc,
    int nchunks, float (&accP)[4][4], float (&accQ)[4][4],
    __half* __restrict__ sm, uint32_t smbase, int& gidx)
{
    const int t = threadIdx.x;
    const uint32_t mbF = smbase + MB_OFF;
    const uint32_t mbE = smbase + MB_OFF + 24;
    if (t == 0) {
        int npre = nchunks < 2 ? nchunks : 2;
        for (int j = 0; j < npre; j++) {
            int idx = gidx + j, s = idx % 3;
            uint32_t ph = (uint32_t)((idx / 3) & 1);
            mbar_wait(mbE + 8 * s, ph);
            mbar_expect(mbF + 8 * s, STAGE_BYTES);
            uint32_t dst = smbase + s * STAGE_BYTES;
            bulkcp(dst, Asrc + (size_t)j * HCH, 32768, mbF + 8 * s);
            bulkcp(dst + 32768, Wsrc + (size_t)j * WCH, 8192, mbF + 8 * s);
        }
    }
    #pragma unroll 1
    for (int i = 0; i < nchunks; i++) {
        int idx = gidx + i, s = idx % 3;
        uint32_t ph = (uint32_t)((idx / 3) & 1);
        mbar_wait(mbF + 8 * s, ph);
        if (t == 0 && i + 2 < nchunks) {
            int i2 = i + 2, idx2 = gidx + i2, s2 = idx2 % 3;
            uint32_t ph2 = (uint32_t)((idx2 / 3) & 1);
            mbar_wait(mbE + 8 * s2, ph2);
            mbar_expect(mbF + 8 * s2, STAGE_BYTES);
            uint32_t dst = smbase + s2 * STAGE_BYTES;
            bulkcp(dst, Asrc + (size_t)i2 * HCH, 32768, mbF + 8 * s2);
            bulkcp(dst + 32768, Wsrc + (size_t)i2 * WCH, 8192, mbF + 8 * s2);
        }
        compute_chunk(sm + s * BUFH, accP, accQ);
        __syncwarp();
        if ((t & 31) == 0) mbar_arrive(mbE + 8 * s);
    }
    gidx += nchunks;
}

// ---------------------------------------------------------------------------
// Cross-khalf reduction + LSTM epilogue. Writes h planes in the pre-swizzled
// chunk layout: [chunk cu][plane][b][64], swz group = (blk&7) ^ (b&7).
// ---------------------------------------------------------------------------
__device__ __forceinline__ void layer_finish(
    float (&accP)[4][4], float (&accQ)[4][4],
    const float* __restrict__ bih, const float* __restrict__ bhh,
    float* __restrict__ c_st, __half* __restrict__ hdst,
    float* __restrict__ hf, int u0, float* __restrict__ sred)
{
    const int lane = threadIdx.x & 31;
    const int wrp  = threadIdx.x >> 5;
    __syncthreads();
    if (wrp >= 8) {
        float* p = sred + ((wrp - 8) * 32 + lane) * 17;
        #pragma unroll
        for (int nt = 0; nt < 4; nt++)
            #pragma unroll
            for (int ii = 0; ii < 4; ii++)
                p[nt * 4 + ii] = accP[nt][ii] + accQ[nt][ii];
    }
    __syncthreads();
    if (wrp < 8) {
        const float* p = sred + (wrp * 32 + lane) * 17;
        float acc[4][4];
        #pragma unroll
        for (int nt = 0; nt < 4; nt++)
            #pragma unroll
            for (int ii = 0; ii < 4; ii++)
                acc[nt][ii] = accP[nt][ii] + accQ[nt][ii] + p[nt * 4 + ii];
        const int g  = lane >> 2;
        const int tg = lane & 3;
        const int cu  = blockIdx.x >> 3;
        const int cg7 = blockIdx.x & 7;
        #pragma unroll
        for (int half_ = 0; half_ < 2; half_++) {
            const int b = wrp * 16 + g + half_ * 8;
            float hn[2];
            #pragma unroll
            for (int pp = 0; pp < 2; pp++) {
                const int u   = u0 + 2 * tg + pp;
                const int idx = half_ * 2 + pp;
                float zi = acc[0][idx] + bih[0 * HH + u] + bhh[0 * HH + u];
                float zf = acc[1][idx] + bih[1 * HH + u] + bhh[1 * HH + u];
                float zg = acc[2][idx] + bih[2 * HH + u] + bhh[2 * HH + u];
                float zo = acc[3][idx] + bih[3 * HH + u] + bhh[3 * HH + u];
                float co = c_st[b * HH + u];
                float cn = sigmf(zf) * co + sigmf(zi) * tanhf(zg);
                hn[pp] = sigmf(zo) * tanhf(cn);
                c_st[b * HH + u] = cn;
                if (hf) hf[b * HH + u] = hn[pp];
            }
            const int o = cu * HCH + b * 64 + ((cg7 ^ (b & 7)) << 3) + 2 * tg;
            __half s00 = __float2half_rn(hn[0]);
            __half s01 = __float2half_rn(hn[1]);
            *(__half2*)(hdst + o) = __halves2half2(s00, s01);
            *(__half2*)(hdst + 8192 + o) = __halves2half2(
                __float2half_rn(hn[0] - __half2float(s00)),
                __float2half_rn(hn[1] - __half2float(s01)));
        }
    }
}

// Decoder: out[b,t,c] = h3[b,:].dec_w[c,:] + dec_b[c]; writes swizzled x chunks.
__device__ __forceinline__ void decoder_phase(
    const float* __restrict__ h3,
    const float* __restrict__ dw, const float* __restrict__ db,
    float* __restrict__ outt, float* __restrict__ sH)
{
    const int t   = threadIdx.x;
    const int bg  = blockIdx.x >> 3;
    const int cg  = blockIdx.x & 7;
    const int rb0 = bg * 8;
    const int cc0 = cg * 22;
    for (int e = t; e < 8 * HH; e += NTHR) {
        int r = e >> 10, k = e & (HH - 1);
        sH[r * SH_LD + k] = h3[(rb0 + r) * HH + k];
    }
    __syncthreads();
    if (t < 8 * 22) {
        int br = t / 22, cc = t % 22;
        int c  = cc0 + cc;
        if (c < CC) {
            const float4* wr = (const float4*)(dw + (size_t)c * HH);
            const float4* hr = (const float4*)(sH + br * SH_LD);
            float s = 0.0f;
            #pragma unroll 4
            for (int k4 = 0; k4 < HH / 4; k4++) {
                float4 w = wr[k4];
                float4 h = hr[k4];
                s += w.x * h.x + w.y * h.y + w.z * h.z + w.w * h.w;
            }
            float o = s + db[c];
            const int b = rb0 + br;
            outt[(size_t)b * (size_t)(TT * CC) + c] = o;
            const int ch = c >> 6, c6 = c & 63;
            const int pos = (((c6 >> 3) ^ (b & 7)) << 3) | (c6 & 7);
            __half s0 = __float2half_rn(o);
            g_xA[ch * HCH + b * 64 + pos] = s0;
            g_xA[ch * HCH + 8192 + b * 64 + pos] =
                __float2half_rn(o - __half2float(s0));
        }
    }
    __syncthreads();
}

// ---------------------------------------------------------------------------
__global__ void __launch_bounds__(NTHR, 1) aclstm_kernel(
    const float* __restrict__ seq,
    const float* __restrict__ w_ih1, const float* __restrict__ w_hh1,
    const float* __restrict__ b_ih1, const float* __restrict__ b_hh1,
    const float* __restrict__ w_ih2, const float* __restrict__ w_hh2,
    const float* __restrict__ b_ih2, const float* __restrict__ b_hh2,
    const float* __restrict__ w_ih3, const float* __restrict__ w_hh3,
    const float* __restrict__ b_ih3, const float* __restrict__ b_hh3,
    const float* __restrict__ dec_w, const float* __restrict__ dec_b,
    const int* __restrict__ gtp, const int* __restrict__ condp,
    float* __restrict__ out)
{
    extern __shared__ __align__(128) unsigned char dynsm[];
    __half* sm   = (__half*)dynsm;
    float*  sred = (float*)dynsm;
    float*  sH   = (float*)dynsm;
    const uint32_t smbase = (uint32_t)__cvta_generic_to_shared(dynsm);
    const int u0 = blockIdx.x * 8;
    const int blk = blockIdx.x;
    const long gtid = blockIdx.x * NTHR + threadIdx.x;
    const long gstr = (long)NBLK * NTHR;

    // ---- mbarrier init + pre-arm empties ----
    if (threadIdx.x == 0) {
        #pragma unroll
        for (int s = 0; s < 3; s++) {
            mbar_init(smbase + MB_OFF + 8 * s, 1);        // full: expect_tx arrival
            mbar_init(smbase + MB_OFF + 24 + 8 * s, 16);  // empty: warp leaders
        }
        asm volatile("fence.proxy.async.shared::cta;" ::: "memory");
    }
    __syncthreads();
    if ((threadIdx.x & 31) == 0) {
        #pragma unroll
        for (int s = 0; s < 3; s++) mbar_arrive(smbase + MB_OFF + 24 + 8 * s);
    }
    __syncthreads();

    // ---- init: zero state/x, pre-split seq, re-layout+split weights ----
    for (long e = gtid; e < BB * HH; e += gstr) {
        #pragma unroll
        for (int l = 0; l < 3; l++) g_c[l][e] = 0.0f;
    }
    for (long e = gtid; e < HLAY; e += gstr) {
        #pragma unroll
        for (int l = 0; l < 3; l++) g_hA[l][0][e] = __ushort_as_half(0);
    }
    for (long e = gtid; e < 3 * HCH; e += gstr)
        g_xA[e] = __ushort_as_half(0);
    // seq chunks (destination-major)
    for (long n = gtid; n < (long)TT * 3 * HCH; n += gstr) {
        int tt = (int)(n / (3 * HCH));
        int r  = (int)(n % (3 * HCH));
        int ch = r / HCH; int r2 = r % HCH;
        int p  = r2 >> 13;                // 8192 halves per plane
        int r3 = r2 & 8191;
        int b  = r3 >> 6;
        int pos = r3 & 63;
        int c  = ch * 64 + (((pos >> 3) ^ (b & 7)) << 3) + (pos & 7);
        float v = (c < CC) ? seq[((size_t)b * TT + tt) * CC + c] : 0.0f;
        __half h = __float2half_rn(v);
        g_seqA[tt][r] = p ? __float2half_rn(v - __half2float(h)) : h;
    }
    // big weights (destination-major; each source element maps to one block)
    for (long n = gtid; n < 5L * NBLK * 16 * WCH; n += gstr) {
        int m   = (int)(n / ((long)NBLK * 16 * WCH));
        long r  = n % ((long)NBLK * 16 * WCH);
        int bl  = (int)(r / (16 * WCH));
        int r2  = (int)(r % (16 * WCH));
        int ch  = r2 / WCH;
        int r3  = r2 % WCH;
        int p   = r3 >> 11;               // 2048 halves per plane
        int nl  = (r3 >> 6) & 31;
        int pos = r3 & 63;
        int kk  = (((pos >> 3) ^ (nl & 7)) << 3) + (pos & 7);
        int k   = ch * 64 + kk;
        int R   = (nl >> 3) * HH + bl * 8 + (nl & 7);
        const float* Wm = (m == 0) ? w_hh1 : (m == 1) ? w_ih2 :
                          (m == 2) ? w_hh2 : (m == 3) ? w_ih3 : w_hh3;
        float v = Wm[(size_t)R * HH + k];
        __half h = __float2half_rn(v);
        g_wb[0][0][n] = p ? __float2half_rn(v - __half2float(h)) : h;
    }
    // w_ih1 (K padded 171 -> 192)
    for (long n = gtid; n < (long)NBLK * 3 * WCH; n += gstr) {
        int bl  = (int)(n / (3 * WCH));
        int r2  = (int)(n % (3 * WCH));
        int ch  = r2 / WCH;
        int r3  = r2 % WCH;
        int p   = r3 >> 11;
        int nl  = (r3 >> 6) & 31;
        int pos = r3 & 63;
        int kk  = (((pos >> 3) ^ (nl & 7)) << 3) + (pos & 7);
        int k   = ch * 64 + kk;
        int R   = (nl >> 3) * HH + bl * 8 + (nl & 7);
        float v = (k < CC) ? w_ih1[(size_t)R * CC + k] : 0.0f;
        __half h = __float2half_rn(v);
        g_w1b[0][n] = p ? __float2half_rn(v - __half2float(h)) : h;
    }
    grid_sync();

    const int gt   = *gtp;
    const int cond = *condp;
    int period = gt + cond;
    if (period < 1) period = 1;

    int gidx = 0;   // global chunk counter (identical across threads)

    #pragma unroll 1
    for (int t = 0; t < TT; t++) {
        const int rd = t & 1, wr = rd ^ 1;
        const bool use_gt = (t % period) < gt;

        float accP[4][4], accQ[4][4];

        // ---- Layer 1 ----
        #pragma unroll
        for (int i = 0; i < 4; i++)
            #pragma unroll
            for (int j = 0; j < 4; j++) { accP[i][j] = 0.0f; accQ[i][j] = 0.0f; }
        const __half* X = use_gt ? g_seqA[t] : g_xA;
        gemm16(X, g_w1b[blk], 3, accP, accQ, sm, smbase, gidx);
        gemm16(g_hA[0][rd], g_wb[0][blk], 16, accP, accQ, sm, smbase, gidx);
        layer_finish(accP, accQ, b_ih1, b_hh1, g_c[0],
                     g_hA[0][wr], (float*)0, u0, sred);
        grid_sync();

        // ---- Layer 2 ----
        #pragma unroll
        for (int i = 0; i < 4; i++)
            #pragma unroll
            for (int j = 0; j < 4; j++) { accP[i][j] = 0.0f; accQ[i][j] = 0.0f; }
        gemm16(g_hA[0][wr], g_wb[1][blk], 16, accP, accQ, sm, smbase, gidx);
        gemm16(g_hA[1][rd], g_wb[2][blk], 16, accP, accQ, sm, smbase, gidx);
        layer_finish(accP, accQ, b_ih2, b_hh2, g_c[1],
                     g_hA[1][wr], (float*)0, u0, sred);
        grid_sync();

        // ---- Layer 3 ----
        #pragma unroll
        for (int i = 0; i < 4; i++)
            #pragma unroll
            for (int j = 0; j < 4; j++) { accP[i][j] = 0.0f; accQ[i][j] = 0.0f; }
        gemm16(g_hA[1][wr], g_wb[3][blk], 16, accP, accQ, sm, smbase, gidx);
        gemm16(g_hA[2][rd], g_wb[4][blk], 16, accP, accQ, sm, smbase, gidx);
        layer_finish(accP, accQ, b_ih3, b_hh3, g_c[2],
                     g_hA[2][wr], g_h3, u0, sred);
        grid_sync();

        // ---- Decoder ----
        __syncthreads();
        decoder_phase(g_h3, dec_w, dec_b, out + (size_t)t * CC, sH);
        grid_sync();   // out[t] + g_xA visible before next step
    }
}

// ---------------------------------------------------------------------------
extern "C" void kernel_launch(void* const* d_in, const int* in_sizes, int n_in,
                              void* d_out, int out_size)
{
    (void)in_sizes; (void)n_in; (void)out_size;
    cudaFuncSetAttribute(aclstm_kernel,
                         cudaFuncAttributeMaxDynamicSharedMemorySize,
                         SMEM_BYTES);
    aclstm_kernel<<<NBLK, NTHR, SMEM_BYTES>>>(
        (const float*)d_in[0],
        (const float*)d_in[1],  (const float*)d_in[2],
        (const float*)d_in[3],  (const float*)d_in[4],
        (const float*)d_in[5],  (const float*)d_in[6],
        (const float*)d_in[7],  (const float*)d_in[8],
        (const float*)d_in[9],  (const float*)d_in[10],
        (const float*)d_in[11], (const float*)d_in[12],
        (const float*)d_in[13], (const float*)d_in[14],
        (const int*)d_in[15],   (const int*)d_in[16],
        (float*)d_out);
}

// round 13
// speedup vs baseline: 3.4969x; 1.1911x over previous
#include <cuda_runtime.h>
#include <cuda_fp16.h>
#include <math.h>
#include <stdint.h>

#define BB   128
#define TT   256
#define HH   1024
#define CC   171
#define NBLK 128
#define NTHR 512
#define SH_LD 1036

#define HCH  16384            // halves per A chunk (2 planes x 128 x 64)
#define HLAY (16 * HCH)
#define WCH  4096             // halves per W chunk (2 planes x 32 x 64)

#define NSTG 4
#define STAGE_BYTES 40960     // A planes 32768 + B planes 8192
#define SM_DEC   (NSTG * STAGE_BYTES)          // 163840 decoder staging
#define SM_MBAR  (SM_DEC + 8 * SH_LD * 4)      // 196992
#define MB_FULL  (SM_MBAR)                     // 4 x 8B
#define MB_EMPTY (SM_MBAR + 32)                // 4 x 8B
#define SM_BIAS  (SM_MBAR + 64)                // 96 floats
#define SMEM_BYTES (SM_BIAS + 96 * 4)

// ---------------- persistent state (module statics, no runtime alloc) ------
__device__ __align__(16) __half g_hA[3][2][HLAY];      // pre-swizzled h chunks
__device__ __align__(16) __half g_xA[3 * HCH];         // self-fed frame chunks
__device__ __align__(16) __half g_seqA[TT][3 * HCH];   // pre-split seq chunks
__device__ __align__(16) __half g_wb[5][NBLK][16 * WCH];
__device__ __align__(16) __half g_w1b[NBLK][3 * WCH];
__device__ float g_h3[BB * HH];
__device__ unsigned long long g_arrive;
__device__ unsigned long long g_release;

// ---------------- grid-wide barrier (monotonic, replay-safe) ---------------
__device__ __forceinline__ void grid_sync() {
    __threadfence();
    __syncthreads();
    if (threadIdx.x == 0) {
        unsigned long long a = atomicAdd(&g_arrive, 1ull) + 1ull;
        if ((a % (unsigned long long)NBLK) == 0ull) {
            __threadfence();
            *(volatile unsigned long long*)&g_release = a;
        } else {
            unsigned long long target =
                ((a + (unsigned long long)NBLK - 1ull) / (unsigned long long)NBLK)
                * (unsigned long long)NBLK;
            while (*(volatile unsigned long long*)&g_release < target) { }
            __threadfence();
        }
    }
    __syncthreads();
}

__device__ __forceinline__ float sigf(float x) {
    return 1.0f / (1.0f + expf(-x));
}

// ---------------- mbarrier / bulk-copy helpers -----------------------------
__device__ __forceinline__ void mbar_init(uint32_t mbar, uint32_t count) {
    asm volatile("mbarrier.init.shared.b64 [%0], %1;"
                 :: "r"(mbar), "r"(count) : "memory");
}
__device__ __forceinline__ void mbar_arrive(uint32_t mbar) {
    asm volatile("mbarrier.arrive.shared.b64 _, [%0];"
                 :: "r"(mbar) : "memory");
}
__device__ __forceinline__ void mbar_expect(uint32_t mbar, uint32_t tx) {
    asm volatile("mbarrier.arrive.expect_tx.shared.b64 _, [%0], %1;"
                 :: "r"(mbar), "r"(tx) : "memory");
}
__device__ __forceinline__ void mbar_wait(uint32_t mbar, uint32_t parity) {
    asm volatile(
        "{\n\t.reg .pred P;\n\t"
        "WL%=:\n\t"
        "mbarrier.try_wait.parity.shared::cta.b64 P, [%0], %1;\n\t"
        "@!P bra WL%=;\n\t}"
        :: "r"(mbar), "r"(parity) : "memory");
}
__device__ __forceinline__ void bulkcp(uint32_t dst, const void* src,
                                       uint32_t bytes, uint32_t mbar) {
    asm volatile(
        "cp.async.bulk.shared::cluster.global.mbarrier::complete_tx::bytes "
        "[%0], [%1], %2, [%3];"
        :: "r"(dst), "l"(src), "r"(bytes), "r"(mbar) : "memory");
}

// ---------------- fragment ops ----------------------------------------------
__device__ __forceinline__ void ldsm4(uint32_t a, uint32_t& r0, uint32_t& r1,
                                      uint32_t& r2, uint32_t& r3) {
    asm volatile("ldmatrix.sync.aligned.m8n8.x4.shared.b16 {%0,%1,%2,%3}, [%4];"
                 : "=r"(r0), "=r"(r1), "=r"(r2), "=r"(r3) : "r"(a));
}
__device__ __forceinline__ void mma16(float* d,
    uint32_t a0, uint32_t a1, uint32_t a2, uint32_t a3,
    uint32_t b0, uint32_t b1)
{
    asm volatile(
        "mma.sync.aligned.m16n8k16.row.col.f32.f16.f16.f32 "
        "{%0,%1,%2,%3}, {%4,%5,%6,%7}, {%8,%9}, {%0,%1,%2,%3};\n"
        : "+f"(d[0]), "+f"(d[1]), "+f"(d[2]), "+f"(d[3])
        : "r"(a0), "r"(a1), "r"(a2), "r"(a3), "r"(b0), "r"(b1));
}

// ---------------------------------------------------------------------------
// Compute one K=64 chunk. Warp wrp: mg = wrp&3 -> rows 32*mg..+31;
// kq = wrp>>2 -> k16 quarter. Tile per warp: m32 x n32 x k16.
// 8 ldmatrix.x4 + 24 mma per warp per chunk. Single fp32 acc set.
// ---------------------------------------------------------------------------
__device__ __forceinline__ void compute_chunk(uint32_t sb,
    const uint32_t (&oa)[2][2], const uint32_t (&ob)[2][2],
    float (&acc)[2][4][4])
{
    uint32_t Ah[8], Al[8], Bh[8], Bl[8];
    ldsm4(sb + oa[0][0], Ah[0], Ah[1], Ah[2], Ah[3]);
    ldsm4(sb + oa[0][1], Ah[4], Ah[5], Ah[6], Ah[7]);
    ldsm4(sb + oa[1][0], Al[0], Al[1], Al[2], Al[3]);
    ldsm4(sb + oa[1][1], Al[4], Al[5], Al[6], Al[7]);
    ldsm4(sb + ob[0][0], Bh[0], Bh[1], Bh[2], Bh[3]);
    ldsm4(sb + ob[0][1], Bh[4], Bh[5], Bh[6], Bh[7]);
    ldsm4(sb + ob[1][0], Bl[0], Bl[1], Bl[2], Bl[3]);
    ldsm4(sb + ob[1][1], Bl[4], Bl[5], Bl[6], Bl[7]);
    #pragma unroll
    for (int mf = 0; mf < 2; mf++) {
        #pragma unroll
        for (int nt = 0; nt < 4; nt++) {
            float* d = acc[mf][nt];
            mma16(d, Ah[4*mf+0], Ah[4*mf+1], Ah[4*mf+2], Ah[4*mf+3],
                  Bh[2*nt], Bh[2*nt+1]);
            mma16(d, Al[4*mf+0], Al[4*mf+1], Al[4*mf+2], Al[4*mf+3],
                  Bh[2*nt], Bh[2*nt+1]);
            mma16(d, Ah[4*mf+0], Ah[4*mf+1], Ah[4*mf+2], Ah[4*mf+3],
                  Bl[2*nt], Bl[2*nt+1]);
        }
    }
}

// ---------------------------------------------------------------------------
// Ring-pipelined GEMM over two segments (A0/W0 n0 chunks, then A1/W1 n1).
// 4 slots, lookahead 3, thread 0 is the bulk-copy producer.
// ---------------------------------------------------------------------------
__device__ __forceinline__ void gemm2(
    const __half* __restrict__ A0s, const __half* __restrict__ W0s, int n0,
    const __half* __restrict__ A1s, const __half* __restrict__ W1s, int n1,
    uint32_t smbase, float (&acc)[2][4][4],
    const uint32_t (&oa)[2][2], const uint32_t (&ob)[2][2], int& gidx)
{
    const int t = threadIdx.x;
    const int ntot = n0 + n1;
    const uint32_t mbF = smbase + MB_FULL;
    const uint32_t mbE = smbase + MB_EMPTY;

    if (t == 0) {
        int npre = ntot < 3 ? ntot : 3;
        for (int j = 0; j < npre; j++) {
            int idx = gidx + j, s = idx & 3;
            mbar_wait(mbE + 8 * s, (uint32_t)((idx >> 2) & 1));
            mbar_expect(mbF + 8 * s, STAGE_BYTES);
            uint32_t dst = smbase + s * STAGE_BYTES;
            const __half* A = (j < n0) ? A0s : A1s;
            const __half* W = (j < n0) ? W0s : W1s;
            int jj = (j < n0) ? j : j - n0;
            bulkcp(dst, A + (size_t)jj * HCH, 32768, mbF + 8 * s);
            bulkcp(dst + 32768, W + (size_t)jj * WCH, 8192, mbF + 8 * s);
        }
    }
    #pragma unroll 1
    for (int i = 0; i < ntot; i++) {
        int idx = gidx + i, s = idx & 3;
        mbar_wait(mbF + 8 * s, (uint32_t)((idx >> 2) & 1));
        if (t == 0 && i + 3 < ntot) {
            int j = i + 3, idx2 = gidx + j, s2 = idx2 & 3;
            mbar_wait(mbE + 8 * s2, (uint32_t)((idx2 >> 2) & 1));
            mbar_expect(mbF + 8 * s2, STAGE_BYTES);
            uint32_t dst = smbase + s2 * STAGE_BYTES;
            const __half* A = (j < n0) ? A0s : A1s;
            const __half* W = (j < n0) ? W0s : W1s;
            int jj = (j < n0) ? j : j - n0;
            bulkcp(dst, A + (size_t)jj * HCH, 32768, mbF + 8 * s2);
            bulkcp(dst + 32768, W + (size_t)jj * WCH, 8192, mbF + 8 * s2);
        }
        compute_chunk(smbase + s * STAGE_BYTES, oa, ob, acc);
        __syncwarp();
        if ((t & 31) == 0) mbar_arrive(mbE + 8 * s);
    }
    gidx += ntot;
}

// ---------------------------------------------------------------------------
// 4-way k-quarter reduction through smem + thread-local LSTM epilogue.
// kq>0 warps dump partials; kq==0 warps (t<128) reduce and finish.
// Thread owns rows {mg*32+mf*16+l/4, +8} x units u0+(l&3)*2+{0,1}; gate = nt.
// ---------------------------------------------------------------------------
__device__ __forceinline__ void layer_finish(
    float (&acc)[2][4][4], const float* __restrict__ sb,
    float (&creg)[8], __half* __restrict__ hdst, float* __restrict__ hf,
    float* __restrict__ scratch)
{
    const int lane = threadIdx.x & 31;
    const int wrp  = threadIdx.x >> 5;
    const int mg = wrp & 3, kq = wrp >> 2;
    __syncthreads();   // all chunk compute done; stage slots idle -> scratch
    if (kq > 0) {
        float* p = scratch + (size_t)(((kq - 1) * 4 + mg) * 32 + lane) * 33;
        #pragma unroll
        for (int mf = 0; mf < 2; mf++)
            #pragma unroll
            for (int nt = 0; nt < 4; nt++)
                #pragma unroll
                for (int ii = 0; ii < 4; ii++)
                    p[mf * 16 + nt * 4 + ii] = acc[mf][nt][ii];
    }
    __syncthreads();
    if (kq == 0) {
        #pragma unroll
        for (int q = 0; q < 3; q++) {
            const float* p = scratch + (size_t)((q * 4 + mg) * 32 + lane) * 33;
            #pragma unroll
            for (int mf = 0; mf < 2; mf++)
                #pragma unroll
                for (int nt = 0; nt < 4; nt++)
                    #pragma unroll
                    for (int ii = 0; ii < 4; ii++)
                        acc[mf][nt][ii] += p[mf * 16 + nt * 4 + ii];
        }
    }
    __syncthreads();   // scratch free for producer reuse
    if (kq == 0) {
        const int cu  = blockIdx.x >> 3;
        const int cg7 = blockIdx.x & 7;
        const int u0  = blockIdx.x * 8;
        const int du0 = (lane & 3) * 2;
        #pragma unroll
        for (int mf = 0; mf < 2; mf++) {
            #pragma unroll
            for (int rh = 0; rh < 2; rh++) {
                const int R = mg * 32 + mf * 16 + rh * 8 + (lane >> 2);
                float hv[2];
                #pragma unroll
                for (int p = 0; p < 2; p++) {
                    const int idx = rh * 2 + p;
                    const int ci  = mf * 4 + rh * 2 + p;
                    float zi = acc[mf][0][idx] + sb[0  + du0 + p];
                    float zf = acc[mf][1][idx] + sb[8  + du0 + p];
                    float zg = acc[mf][2][idx] + sb[16 + du0 + p];
                    float zo = acc[mf][3][idx] + sb[24 + du0 + p];
                    float cn = sigf(zf) * creg[ci] + sigf(zi) * tanhf(zg);
                    creg[ci] = cn;
                    hv[p] = sigf(zo) * tanhf(cn);
                }
                const int o = cu * HCH + R * 64 + ((cg7 ^ (R & 7)) << 3) + du0;
                __half a0 = __float2half_rn(hv[0]);
                __half a1 = __float2half_rn(hv[1]);
                *(__half2*)(hdst + o) = __halves2half2(a0, a1);
                *(__half2*)(hdst + 8192 + o) = __halves2half2(
                    __float2half_rn(hv[0] - __half2float(a0)),
                    __float2half_rn(hv[1] - __half2float(a1)));
                if (hf)
                    *(float2*)(hf + (size_t)R * HH + u0 + du0) =
                        make_float2(hv[0], hv[1]);
            }
        }
    }
}

// Decoder: out[b,t,c] = h3[b,:].dec_w[c,:] + dec_b[c]; writes swizzled x chunks.
__device__ __forceinline__ void decoder_phase(
    const float* __restrict__ h3,
    const float* __restrict__ dw, const float* __restrict__ db,
    float* __restrict__ outt, float* __restrict__ sH)
{
    const int t   = threadIdx.x;
    const int bg  = blockIdx.x >> 3;
    const int cg  = blockIdx.x & 7;
    const int rb0 = bg * 8;
    const int cc0 = cg * 22;
    for (int e = t; e < 8 * HH; e += NTHR) {
        int r = e >> 10, k = e & (HH - 1);
        sH[r * SH_LD + k] = h3[(rb0 + r) * HH + k];
    }
    __syncthreads();
    if (t < 8 * 22) {
        int br = t / 22, cc = t % 22;
        int c  = cc0 + cc;
        if (c < CC) {
            const float4* wr = (const float4*)(dw + (size_t)c * HH);
            const float4* hr = (const float4*)(sH + br * SH_LD);
            float s = 0.0f;
            #pragma unroll 4
            for (int k4 = 0; k4 < HH / 4; k4++) {
                float4 w = wr[k4];
                float4 h = hr[k4];
                s += w.x * h.x + w.y * h.y + w.z * h.z + w.w * h.w;
            }
            float o = s + db[c];
            const int b = rb0 + br;
            outt[(size_t)b * (size_t)(TT * CC) + c] = o;
            const int ch = c >> 6, c6 = c & 63;
            const int pos = (((c6 >> 3) ^ (b & 7)) << 3) | (c6 & 7);
            __half s0 = __float2half_rn(o);
            g_xA[ch * HCH + b * 64 + pos] = s0;
            g_xA[ch * HCH + 8192 + b * 64 + pos] =
                __float2half_rn(o - __half2float(s0));
        }
    }
    __syncthreads();
}

// ---------------------------------------------------------------------------
__global__ void __launch_bounds__(NTHR, 1) aclstm_kernel(
    const float* __restrict__ seq,
    const float* __restrict__ w_ih1, const float* __restrict__ w_hh1,
    const float* __restrict__ b_ih1, const float* __restrict__ b_hh1,
    const float* __restrict__ w_ih2, const float* __restrict__ w_hh2,
    const float* __restrict__ b_ih2, const float* __restrict__ b_hh2,
    const float* __restrict__ w_ih3, const float* __restrict__ w_hh3,
    const float* __restrict__ b_ih3, const float* __restrict__ b_hh3,
    const float* __restrict__ dec_w, const float* __restrict__ dec_b,
    const int* __restrict__ gtp, const int* __restrict__ condp,
    float* __restrict__ out)
{
    extern __shared__ __align__(1024) unsigned char dynsm[];
    const uint32_t smbase = (uint32_t)__cvta_generic_to_shared(dynsm);
    float* sH      = (float*)(dynsm + SM_DEC);
    float* scratch = (float*)dynsm;                 // stage slots (idle) reuse
    const float* sbias = (const float*)(dynsm + SM_BIAS);
    const int t   = threadIdx.x;
    const int blk = blockIdx.x;
    const int u0  = blk * 8;
    const long gtid = (long)blk * NTHR + t;
    const long gstr = (long)NBLK * NTHR;

    // ---- mbarrier init + bias staging ----
    if (t == 0) {
        #pragma unroll
        for (int s = 0; s < NSTG; s++) {
            mbar_init(smbase + MB_FULL + 8 * s, 1);
            mbar_init(smbase + MB_EMPTY + 8 * s, 16);
        }
        asm volatile("fence.proxy.async.shared::cta;" ::: "memory");
    }
    if (t < 96) {
        int l = t >> 5, gate = (t & 31) >> 3, du = t & 7;
        const float* bi = (l == 0) ? b_ih1 : (l == 1) ? b_ih2 : b_ih3;
        const float* bh = (l == 0) ? b_hh1 : (l == 1) ? b_hh2 : b_hh3;
        ((float*)(dynsm + SM_BIAS))[t] =
            bi[gate * HH + u0 + du] + bh[gate * HH + u0 + du];
    }
    __syncthreads();
    if ((t & 31) == 0) {
        #pragma unroll
        for (int s = 0; s < NSTG; s++) mbar_arrive(smbase + MB_EMPTY + 8 * s);
    }
    __syncthreads();

    // ---- per-thread fragment byte offsets (within a stage slot) ----
    const int lane = t & 31, wrp = t >> 5;
    const int mg = wrp & 3, kq = wrp >> 2;
    const int mat = lane >> 3, rr = lane & 7;
    uint32_t oa[2][2], ob[2][2];
    #pragma unroll
    for (int mf = 0; mf < 2; mf++) {
        int R  = mg * 32 + mf * 16 + ((mat & 1) << 3) + rr;
        int kg = kq * 2 + (mat >> 1);
        uint32_t base = (uint32_t)(R * 128 + ((kg ^ (R & 7)) << 4));
        oa[0][mf] = base;
        oa[1][mf] = base + 16384;
    }
    #pragma unroll
    for (int ntp = 0; ntp < 2; ntp++) {
        int nt = ntp * 2 + (mat >> 1);
        int kg = kq * 2 + (mat & 1);
        int n  = nt * 8 + rr;
        uint32_t base = (uint32_t)(32768 + n * 128 + ((kg ^ (n & 7)) << 4));
        ob[0][ntp] = base;
        ob[1][ntp] = base + 4096;
    }

    // ---- init: zero h/x, pre-split seq, re-layout+split weights ----
    for (long e = gtid; e < HLAY; e += gstr) {
        #pragma unroll
        for (int l = 0; l < 3; l++) g_hA[l][0][e] = __ushort_as_half(0);
    }
    for (long e = gtid; e < 3 * HCH; e += gstr)
        g_xA[e] = __ushort_as_half(0);
    for (long n = gtid; n < (long)TT * 3 * HCH; n += gstr) {
        int tt = (int)(n / (3 * HCH));
        int r  = (int)(n % (3 * HCH));
        int ch = r / HCH; int r2 = r % HCH;
        int p  = r2 >> 13;
        int r3 = r2 & 8191;
        int b  = r3 >> 6;
        int pos = r3 & 63;
        int c  = ch * 64 + (((pos >> 3) ^ (b & 7)) << 3) + (pos & 7);
        float v = (c < CC) ? seq[((size_t)b * TT + tt) * CC + c] : 0.0f;
        __half h = __float2half_rn(v);
        g_seqA[tt][r] = p ? __float2half_rn(v - __half2float(h)) : h;
    }
    for (long n = gtid; n < 5L * NBLK * 16 * WCH; n += gstr) {
        int m   = (int)(n / ((long)NBLK * 16 * WCH));
        long r  = n % ((long)NBLK * 16 * WCH);
        int bl  = (int)(r / (16 * WCH));
        int r2  = (int)(r % (16 * WCH));
        int ch  = r2 / WCH;
        int r3  = r2 % WCH;
        int p   = r3 >> 11;
        int nl  = (r3 >> 6) & 31;
        int pos = r3 & 63;
        int kk  = (((pos >> 3) ^ (nl & 7)) << 3) + (pos & 7);
        int k   = ch * 64 + kk;
        int R   = (nl >> 3) * HH + bl * 8 + (nl & 7);
        const float* Wm = (m == 0) ? w_hh1 : (m == 1) ? w_ih2 :
                          (m == 2) ? w_hh2 : (m == 3) ? w_ih3 : w_hh3;
        float v = Wm[(size_t)R * HH + k];
        __half h = __float2half_rn(v);
        g_wb[0][0][n] = p ? __float2half_rn(v - __half2float(h)) : h;
    }
    for (long n = gtid; n < (long)NBLK * 3 * WCH; n += gstr) {
        int bl  = (int)(n / (3 * WCH));
        int r2  = (int)(n % (3 * WCH));
        int ch  = r2 / WCH;
        int r3  = r2 % WCH;
        int p   = r3 >> 11;
        int nl  = (r3 >> 6) & 31;
        int pos = r3 & 63;
        int kk  = (((pos >> 3) ^ (nl & 7)) << 3) + (pos & 7);
        int k   = ch * 64 + kk;
        int R   = (nl >> 3) * HH + bl * 8 + (nl & 7);
        float v = (k < CC) ? w_ih1[(size_t)R * CC + k] : 0.0f;
        __half h = __float2half_rn(v);
        g_w1b[0][n] = p ? __float2half_rn(v - __half2float(h)) : h;
    }
    grid_sync();

    const int gt   = *gtp;
    const int cond = *condp;
    int period = gt + cond;
    if (period < 1) period = 1;

    int gidx = 0;
    float c1[8], c2[8], c3[8];
    #pragma unroll
    for (int i = 0; i < 8; i++) { c1[i] = 0.0f; c2[i] = 0.0f; c3[i] = 0.0f; }

    #pragma unroll 1
    for (int ts = 0; ts < TT; ts++) {
        const int rd = ts & 1, wr = rd ^ 1;
        const bool use_gt = (ts % period) < gt;
        const __half* X = use_gt ? g_seqA[ts] : g_xA;

        float acc[2][4][4];

        // ---- Layer 1 ----
        #pragma unroll
        for (int i = 0; i < 2; i++)
            #pragma unroll
            for (int j = 0; j < 4; j++)
                #pragma unroll
                for (int k = 0; k < 4; k++) acc[i][j][k] = 0.0f;
        gemm2(X, g_w1b[blk], 3, g_hA[0][rd], g_wb[0][blk], 16,
              smbase, acc, oa, ob, gidx);
        layer_finish(acc, sbias + 0, c1, g_hA[0][wr], (float*)0, scratch);
        grid_sync();

        // ---- Layer 2 ----
        #pragma unroll
        for (int i = 0; i < 2; i++)
            #pragma unroll
            for (int j = 0; j < 4; j++)
                #pragma unroll
                for (int k = 0; k < 4; k++) acc[i][j][k] = 0.0f;
        gemm2(g_hA[0][wr], g_wb[1][blk], 16, g_hA[1][rd], g_wb[2][blk], 16,
              smbase, acc, oa, ob, gidx);
        layer_finish(acc, sbias + 32, c2, g_hA[1][wr], (float*)0, scratch);
        grid_sync();

        // ---- Layer 3 ----
        #pragma unroll
        for (int i = 0; i < 2; i++)
            #pragma unroll
            for (int j = 0; j < 4; j++)
                #pragma unroll
                for (int k = 0; k < 4; k++) acc[i][j][k] = 0.0f;
        gemm2(g_hA[1][wr], g_wb[3][blk], 16, g_hA[2][rd], g_wb[4][blk], 16,
              smbase, acc, oa, ob, gidx);
        layer_finish(acc, sbias + 64, c3, g_hA[2][wr], g_h3, scratch);
        grid_sync();

        // ---- Decoder ----
        decoder_phase(g_h3, dec_w, dec_b, out + (size_t)ts * CC, sH);
        grid_sync();
    }
}

// ---------------------------------------------------------------------------
extern "C" void kernel_launch(void* const* d_in, const int* in_sizes, int n_in,
                              void* d_out, int out_size)
{
    (void)in_sizes; (void)n_in; (void)out_size;
    cudaFuncSetAttribute(aclstm_kernel,
                         cudaFuncAttributeMaxDynamicSharedMemorySize,
                         SMEM_BYTES);
    aclstm_kernel<<<NBLK, NTHR, SMEM_BYTES>>>(
        (const float*)d_in[0],
        (const float*)d_in[1],  (const float*)d_in[2],
        (const float*)d_in[3],  (const float*)d_in[4],
        (const float*)d_in[5],  (const float*)d_in[6],
        (const float*)d_in[7],  (const float*)d_in[8],
        (const float*)d_in[9],  (const float*)d_in[10],
        (const float*)d_in[11], (const float*)d_in[12],
        (const float*)d_in[13], (const float*)d_in[14],
        (const int*)d_in[15],   (const int*)d_in[16],
        (float*)d_out);
}

// round 14
// speedup vs baseline: 3.6732x; 1.0504x over previous
#include <cuda_runtime.h>
#include <cuda_fp16.h>
#include <math.h>
#include <stdint.h>

#define BB   128
#define TT   256
#define HH   1024
#define CC   171
#define NBLK 128
#define NTHR 512
#define SH_LD 1036

#define HCH  16384            // halves per K64 A chunk (2 planes x 128 x 64)
#define HLAY (16 * HCH)
#define WCH  4096             // halves per K64 W chunk (2 planes x 32 x 64)

#define NSTG 2
#define STAGE_BYTES 81920     // K128 slot: A 65536 + B 16384
#define SM_MBAR  (NSTG * STAGE_BYTES)   // 163840
#define MB_FULL  (SM_MBAR)              // 2 x 8B
#define MB_EMPTY (SM_MBAR + 16)         // 2 x 8B
#define SM_BIAS  (SM_MBAR + 64)         // 96 floats
#define SM_C     (SM_BIAS + 384)        // 3 x 1024 floats
#define SMEM_BYTES (SM_C + 12288)

// ---------------- persistent state (module statics, no runtime alloc) ------
__device__ __align__(16) __half g_hA[3][2][HLAY];      // pre-swizzled h chunks
__device__ __align__(16) __half g_xA[4 * HCH];         // self-fed frame (padded)
__device__ __align__(16) __half g_seqA[TT][4 * HCH];   // pre-split seq (padded)
__device__ __align__(16) __half g_wb[5][NBLK][16 * WCH];
__device__ __align__(16) __half g_w1b[NBLK][4 * WCH];
__device__ float g_h3[BB * HH];
__device__ unsigned long long g_arrive;
__device__ unsigned long long g_release;

// ---------------- grid-wide barrier (monotonic, replay-safe) ---------------
__device__ __forceinline__ void grid_sync() {
    __threadfence();
    __syncthreads();
    if (threadIdx.x == 0) {
        unsigned long long a = atomicAdd(&g_arrive, 1ull) + 1ull;
        if ((a % (unsigned long long)NBLK) == 0ull) {
            __threadfence();
            *(volatile unsigned long long*)&g_release = a;
        } else {
            unsigned long long target =
                ((a + (unsigned long long)NBLK - 1ull) / (unsigned long long)NBLK)
                * (unsigned long long)NBLK;
            while (*(volatile unsigned long long*)&g_release < target) { }
            __threadfence();
        }
    }
    __syncthreads();
}

__device__ __forceinline__ float sigf(float x) {
    return 1.0f / (1.0f + __expf(-x));
}
__device__ __forceinline__ float tanhfast(float x) {
    return 1.0f - 2.0f / (__expf(2.0f * x) + 1.0f);
}

// ---------------- mbarrier / bulk-copy helpers -----------------------------
__device__ __forceinline__ void mbar_init(uint32_t mbar, uint32_t count) {
    asm volatile("mbarrier.init.shared.b64 [%0], %1;"
                 :: "r"(mbar), "r"(count) : "memory");
}
__device__ __forceinline__ void mbar_arrive(uint32_t mbar) {
    asm volatile("mbarrier.arrive.shared.b64 _, [%0];"
                 :: "r"(mbar) : "memory");
}
__device__ __forceinline__ void mbar_expect(uint32_t mbar, uint32_t tx) {
    asm volatile("mbarrier.arrive.expect_tx.shared.b64 _, [%0], %1;"
                 :: "r"(mbar), "r"(tx) : "memory");
}
__device__ __forceinline__ void mbar_wait(uint32_t mbar, uint32_t parity) {
    asm volatile(
        "{\n\t.reg .pred P;\n\t"
        "WL%=:\n\t"
        "mbarrier.try_wait.parity.shared::cta.b64 P, [%0], %1;\n\t"
        "@!P bra WL%=;\n\t}"
        :: "r"(mbar), "r"(parity) : "memory");
}
__device__ __forceinline__ void bulkcp(uint32_t dst, const void* src,
                                       uint32_t bytes, uint32_t mbar) {
    asm volatile(
        "cp.async.bulk.shared::cluster.global.mbarrier::complete_tx::bytes "
        "[%0], [%1], %2, [%3];"
        :: "r"(dst), "l"(src), "r"(bytes), "r"(mbar) : "memory");
}

// ---------------- fragment ops ----------------------------------------------
__device__ __forceinline__ void ldsm4(uint32_t a, uint32_t& r0, uint32_t& r1,
                                      uint32_t& r2, uint32_t& r3) {
    asm volatile("ldmatrix.sync.aligned.m8n8.x4.shared.b16 {%0,%1,%2,%3}, [%4];"
                 : "=r"(r0), "=r"(r1), "=r"(r2), "=r"(r3) : "r"(a));
}
__device__ __forceinline__ void mma16(float* d,
    uint32_t a0, uint32_t a1, uint32_t a2, uint32_t a3,
    uint32_t b0, uint32_t b1)
{
    asm volatile(
        "mma.sync.aligned.m16n8k16.row.col.f32.f16.f16.f32 "
        "{%0,%1,%2,%3}, {%4,%5,%6,%7}, {%8,%9}, {%0,%1,%2,%3};\n"
        : "+f"(d[0]), "+f"(d[1]), "+f"(d[2]), "+f"(d[3])
        : "r"(a0), "r"(a1), "r"(a2), "r"(a3), "r"(b0), "r"(b1));
}

// ---------------------------------------------------------------------------
// Compute one K64 sub-chunk. Warp wrp: mg = wrp&3 -> rows 32*mg..+31;
// kq = wrp>>2 -> k16 quarter. Tile per warp: m32 x n32 x k16.
// ---------------------------------------------------------------------------
__device__ __forceinline__ void compute_sub(uint32_t aB, uint32_t bB,
    const uint32_t (&oa)[2][2], const uint32_t (&ob)[2][2],
    float (&acc)[2][4][4])
{
    uint32_t Ah[8], Al[8], Bh[8], Bl[8];
    ldsm4(aB + oa[0][0], Ah[0], Ah[1], Ah[2], Ah[3]);
    ldsm4(aB + oa[0][1], Ah[4], Ah[5], Ah[6], Ah[7]);
    ldsm4(aB + oa[1][0], Al[0], Al[1], Al[2], Al[3]);
    ldsm4(aB + oa[1][1], Al[4], Al[5], Al[6], Al[7]);
    ldsm4(bB + ob[0][0], Bh[0], Bh[1], Bh[2], Bh[3]);
    ldsm4(bB + ob[0][1], Bh[4], Bh[5], Bh[6], Bh[7]);
    ldsm4(bB + ob[1][0], Bl[0], Bl[1], Bl[2], Bl[3]);
    ldsm4(bB + ob[1][1], Bl[4], Bl[5], Bl[6], Bl[7]);
    #pragma unroll
    for (int mf = 0; mf < 2; mf++) {
        #pragma unroll
        for (int nt = 0; nt < 4; nt++) {
            float* d = acc[mf][nt];
            mma16(d, Ah[4*mf+0], Ah[4*mf+1], Ah[4*mf+2], Ah[4*mf+3],
                  Bh[2*nt], Bh[2*nt+1]);
            mma16(d, Al[4*mf+0], Al[4*mf+1], Al[4*mf+2], Al[4*mf+3],
                  Bh[2*nt], Bh[2*nt+1]);
            mma16(d, Ah[4*mf+0], Ah[4*mf+1], Ah[4*mf+2], Ah[4*mf+3],
                  Bl[2*nt], Bl[2*nt+1]);
        }
    }
}

// ---------------------------------------------------------------------------
// Ring-pipelined GEMM over two segments in K128 slots (2 slots, lookahead 1).
// Slot = 2 consecutive K64 chunks: A (2*HCH halves) + W (2*WCH halves).
// ---------------------------------------------------------------------------
__device__ __forceinline__ void gemm2(
    const __half* __restrict__ A0s, const __half* __restrict__ W0s, int n0,
    const __half* __restrict__ A1s, const __half* __restrict__ W1s, int n1,
    uint32_t smbase, float (&acc)[2][4][4],
    const uint32_t (&oa)[2][2], const uint32_t (&ob)[2][2], int& gidx)
{
    const int t = threadIdx.x;
    const int ntot = n0 + n1;
    const uint32_t mbF = smbase + MB_FULL;
    const uint32_t mbE = smbase + MB_EMPTY;

    if (t == 0) {   // prefetch slot for first chunk
        int idx = gidx, s = idx & 1;
        mbar_wait(mbE + 8 * s, (uint32_t)((idx >> 1) & 1));
        mbar_expect(mbF + 8 * s, STAGE_BYTES);
        uint32_t dst = smbase + s * STAGE_BYTES;
        bulkcp(dst, A0s, 65536, mbF + 8 * s);
        bulkcp(dst + 65536, W0s, 16384, mbF + 8 * s);
    }
    #pragma unroll 1
    for (int i = 0; i < ntot; i++) {
        int idx = gidx + i, s = idx & 1;
        mbar_wait(mbF + 8 * s, (uint32_t)((idx >> 1) & 1));
        if (t == 0 && i + 1 < ntot) {
            int j = i + 1, idx2 = gidx + j, s2 = idx2 & 1;
            mbar_wait(mbE + 8 * s2, (uint32_t)((idx2 >> 1) & 1));
            mbar_expect(mbF + 8 * s2, STAGE_BYTES);
            uint32_t dst = smbase + s2 * STAGE_BYTES;
            const __half* A = (j < n0) ? A0s : A1s;
            const __half* W = (j < n0) ? W0s : W1s;
            int jj = (j < n0) ? j : j - n0;
            bulkcp(dst, A + (size_t)jj * (2 * HCH), 65536, mbF + 8 * s2);
            bulkcp(dst + 65536, W + (size_t)jj * (2 * WCH), 16384,
                   mbF + 8 * s2);
        }
        uint32_t slot = smbase + s * STAGE_BYTES;
        compute_sub(slot,         slot + 65536, oa, ob, acc);
        compute_sub(slot + 32768, slot + 73728, oa, ob, acc);
        __syncwarp();
        if ((t & 31) == 0) mbar_arrive(mbE + 8 * s);
    }
    gidx += ntot;
}

// ---------------------------------------------------------------------------
// 4-way k-quarter reduction + thread-local LSTM epilogue (c-state in smem).
// ---------------------------------------------------------------------------
__device__ __forceinline__ void layer_finish(
    float (&acc)[2][4][4], const float* __restrict__ sb,
    float* __restrict__ cmem, __half* __restrict__ hdst,
    float* __restrict__ hf, float* __restrict__ scratch)
{
    const int lane = threadIdx.x & 31;
    const int wrp  = threadIdx.x >> 5;
    const int mg = wrp & 3, kq = wrp >> 2;
    __syncthreads();   // all compute done; stage slots idle -> scratch
    if (kq > 0) {
        float* p = scratch + (size_t)(((kq - 1) * 4 + mg) * 32 + lane) * 33;
        #pragma unroll
        for (int mf = 0; mf < 2; mf++)
            #pragma unroll
            for (int nt = 0; nt < 4; nt++)
                #pragma unroll
                for (int ii = 0; ii < 4; ii++)
                    p[mf * 16 + nt * 4 + ii] = acc[mf][nt][ii];
    }
    __syncthreads();
    if (kq == 0) {
        #pragma unroll
        for (int q = 0; q < 3; q++) {
            const float* p = scratch + (size_t)((q * 4 + mg) * 32 + lane) * 33;
            #pragma unroll
            for (int mf = 0; mf < 2; mf++)
                #pragma unroll
                for (int nt = 0; nt < 4; nt++)
                    #pragma unroll
                    for (int ii = 0; ii < 4; ii++)
                        acc[mf][nt][ii] += p[mf * 16 + nt * 4 + ii];
        }
    }
    __syncthreads();   // scratch free for producer reuse
    if (kq == 0) {
        const int tt  = threadIdx.x;   // < 128 here
        const int cu  = blockIdx.x >> 3;
        const int cg7 = blockIdx.x & 7;
        const int u0  = blockIdx.x * 8;
        const int du0 = (lane & 3) * 2;
        #pragma unroll
        for (int mf = 0; mf < 2; mf++) {
            #pragma unroll
            for (int rh = 0; rh < 2; rh++) {
                const int R = mg * 32 + mf * 16 + rh * 8 + (lane >> 2);
                float hv[2];
                #pragma unroll
                for (int p = 0; p < 2; p++) {
                    const int idx = rh * 2 + p;
                    const int ci  = mf * 4 + rh * 2 + p;
                    float zi = acc[mf][0][idx] + sb[0  + du0 + p];
                    float zf = acc[mf][1][idx] + sb[8  + du0 + p];
                    float zg = acc[mf][2][idx] + sb[16 + du0 + p];
                    float zo = acc[mf][3][idx] + sb[24 + du0 + p];
                    float co = cmem[ci * 128 + tt];
                    float cn = sigf(zf) * co + sigf(zi) * tanhfast(zg);
                    cmem[ci * 128 + tt] = cn;
                    hv[p] = sigf(zo) * tanhfast(cn);
                }
                const int o = cu * HCH + R * 64 + ((cg7 ^ (R & 7)) << 3) + du0;
                __half a0 = __float2half_rn(hv[0]);
                __half a1 = __float2half_rn(hv[1]);
                *(__half2*)(hdst + o) = __halves2half2(a0, a1);
                *(__half2*)(hdst + 8192 + o) = __halves2half2(
                    __float2half_rn(hv[0] - __half2float(a0)),
                    __float2half_rn(hv[1] - __half2float(a1)));
                if (hf)
                    *(float2*)(hf + (size_t)R * HH + u0 + du0) =
                        make_float2(hv[0], hv[1]);
            }
        }
    }
}

// Decoder: 2-way k-split over 352 threads; writes out + swizzled x chunks.
__device__ __forceinline__ void decoder_phase(
    const float* __restrict__ h3,
    const float* __restrict__ dw, const float* __restrict__ db,
    float* __restrict__ outt, float* __restrict__ sH)
{
    const int t   = threadIdx.x;
    const int bg  = blockIdx.x >> 3;
    const int cg  = blockIdx.x & 7;
    const int rb0 = bg * 8;
    const int cc0 = cg * 22;
    for (int e = t; e < 8 * HH; e += NTHR) {
        int r = e >> 10, k = e & (HH - 1);
        sH[r * SH_LD + k] = h3[(rb0 + r) * HH + k];
    }
    __syncthreads();
    if (t < 352) {
        const int idx = t >> 1, p = t & 1;
        const int br = idx / 22, cc = idx % 22;
        const int c  = cc0 + cc;
        float s = 0.0f;
        if (c < CC) {
            const float4* wr = (const float4*)(dw + (size_t)c * HH) + p * 128;
            const float4* hr = (const float4*)(sH + br * SH_LD) + p * 128;
            #pragma unroll 4
            for (int k4 = 0; k4 < 128; k4++) {
                float4 w = wr[k4];
                float4 h = hr[k4];
                s += w.x * h.x + w.y * h.y + w.z * h.z + w.w * h.w;
            }
        }
        s += __shfl_xor_sync(0xFFFFFFFFu, s, 1);
        if (p == 0 && c < CC) {
            float o = s + db[c];
            const int b = rb0 + br;
            outt[(size_t)b * (size_t)(TT * CC) + c] = o;
            const int ch = c >> 6, c6 = c & 63;
            const int pos = (((c6 >> 3) ^ (b & 7)) << 3) | (c6 & 7);
            __half s0 = __float2half_rn(o);
            g_xA[ch * HCH + b * 64 + pos] = s0;
            g_xA[ch * HCH + 8192 + b * 64 + pos] =
                __float2half_rn(o - __half2float(s0));
        }
    }
    __syncthreads();
}

// ---------------------------------------------------------------------------
__global__ void __launch_bounds__(NTHR, 1) aclstm_kernel(
    const float* __restrict__ seq,
    const float* __restrict__ w_ih1, const float* __restrict__ w_hh1,
    const float* __restrict__ b_ih1, const float* __restrict__ b_hh1,
    const float* __restrict__ w_ih2, const float* __restrict__ w_hh2,
    const float* __restrict__ b_ih2, const float* __restrict__ b_hh2,
    const float* __restrict__ w_ih3, const float* __restrict__ w_hh3,
    const float* __restrict__ b_ih3, const float* __restrict__ b_hh3,
    const float* __restrict__ dec_w, const float* __restrict__ dec_b,
    const int* __restrict__ gtp, const int* __restrict__ condp,
    float* __restrict__ out)
{
    extern __shared__ __align__(1024) unsigned char dynsm[];
    const uint32_t smbase = (uint32_t)__cvta_generic_to_shared(dynsm);
    float* sH      = (float*)dynsm;     // decoder staging overlays stage slots
    float* scratch = (float*)dynsm;     // reduction scratch overlays, too
    const float* sbias = (const float*)(dynsm + SM_BIAS);
    float* cbase = (float*)(dynsm + SM_C);
    const int t   = threadIdx.x;
    const int blk = blockIdx.x;
    const int u0  = blk * 8;
    const long gtid = (long)blk * NTHR + t;
    const long gstr = (long)NBLK * NTHR;

    // ---- mbarrier init + bias staging + c zero ----
    if (t == 0) {
        #pragma unroll
        for (int s = 0; s < NSTG; s++) {
            mbar_init(smbase + MB_FULL + 8 * s, 1);
            mbar_init(smbase + MB_EMPTY + 8 * s, 16);
        }
        asm volatile("fence.proxy.async.shared::cta;" ::: "memory");
    }
    if (t < 96) {
        int l = t >> 5, gate = (t & 31) >> 3, du = t & 7;
        const float* bi = (l == 0) ? b_ih1 : (l == 1) ? b_ih2 : b_ih3;
        const float* bh = (l == 0) ? b_hh1 : (l == 1) ? b_hh2 : b_hh3;
        ((float*)(dynsm + SM_BIAS))[t] =
            bi[gate * HH + u0 + du] + bh[gate * HH + u0 + du];
    }
    if (t < 128) {
        #pragma unroll
        for (int i = 0; i < 24; i++) cbase[i * 128 + t] = 0.0f;
    }
    __syncthreads();
    if ((t & 31) == 0) {
        #pragma unroll
        for (int s = 0; s < NSTG; s++) mbar_arrive(smbase + MB_EMPTY + 8 * s);
    }
    __syncthreads();

    // ---- per-thread fragment byte offsets (relative to A/B region bases) ----
    const int lane = t & 31, wrp = t >> 5;
    const int mg = wrp & 3, kq = wrp >> 2;
    const int mat = lane >> 3, rr = lane & 7;
    uint32_t oa[2][2], ob[2][2];
    #pragma unroll
    for (int mf = 0; mf < 2; mf++) {
        int R  = mg * 32 + mf * 16 + ((mat & 1) << 3) + rr;
        int kg = kq * 2 + (mat >> 1);
        uint32_t base = (uint32_t)(R * 128 + ((kg ^ (R & 7)) << 4));
        oa[0][mf] = base;
        oa[1][mf] = base + 16384;
    }
    #pragma unroll
    for (int ntp = 0; ntp < 2; ntp++) {
        int nt = ntp * 2 + (mat >> 1);
        int kg = kq * 2 + (mat & 1);
        int n  = nt * 8 + rr;
        uint32_t base = (uint32_t)(n * 128 + ((kg ^ (n & 7)) << 4));
        ob[0][ntp] = base;
        ob[1][ntp] = base + 4096;
    }

    // ---- init: zero h/x, pre-split seq, re-layout+split weights ----
    for (long e = gtid; e < HLAY; e += gstr) {
        #pragma unroll
        for (int l = 0; l < 3; l++) g_hA[l][0][e] = __ushort_as_half(0);
    }
    for (long e = gtid; e < 4 * HCH; e += gstr)
        g_xA[e] = __ushort_as_half(0);
    for (long n = gtid; n < (long)TT * 4 * HCH; n += gstr) {
        int tt = (int)(n / (4 * HCH));
        int r  = (int)(n % (4 * HCH));
        int ch = r / HCH; int r2 = r % HCH;
        int p  = r2 >> 13;
        int r3 = r2 & 8191;
        int b  = r3 >> 6;
        int pos = r3 & 63;
        int c  = ch * 64 + (((pos >> 3) ^ (b & 7)) << 3) + (pos & 7);
        float v = (c < CC) ? seq[((size_t)b * TT + tt) * CC + c] : 0.0f;
        __half h = __float2half_rn(v);
        g_seqA[tt][r] = p ? __float2half_rn(v - __half2float(h)) : h;
    }
    for (long n = gtid; n < 5L * NBLK * 16 * WCH; n += gstr) {
        int m   = (int)(n / ((long)NBLK * 16 * WCH));
        long r  = n % ((long)NBLK * 16 * WCH);
        int bl  = (int)(r / (16 * WCH));
        int r2  = (int)(r % (16 * WCH));
        int ch  = r2 / WCH;
        int r3  = r2 % WCH;
        int p   = r3 >> 11;
        int nl  = (r3 >> 6) & 31;
        int pos = r3 & 63;
        int kk  = (((pos >> 3) ^ (nl & 7)) << 3) + (pos & 7);
        int k   = ch * 64 + kk;
        int R   = (nl >> 3) * HH + bl * 8 + (nl & 7);
        const float* Wm = (m == 0) ? w_hh1 : (m == 1) ? w_ih2 :
                          (m == 2) ? w_hh2 : (m == 3) ? w_ih3 : w_hh3;
        float v = Wm[(size_t)R * HH + k];
        __half h = __float2half_rn(v);
        g_wb[0][0][n] = p ? __float2half_rn(v - __half2float(h)) : h;
    }
    for (long n = gtid; n < (long)NBLK * 4 * WCH; n += gstr) {
        int bl  = (int)(n / (4 * WCH));
        int r2  = (int)(n % (4 * WCH));
        int ch  = r2 / WCH;
        int r3  = r2 % WCH;
        int p   = r3 >> 11;
        int nl  = (r3 >> 6) & 31;
        int pos = r3 & 63;
        int kk  = (((pos >> 3) ^ (nl & 7)) << 3) + (pos & 7);
        int k   = ch * 64 + kk;
        int R   = (nl >> 3) * HH + bl * 8 + (nl & 7);
        float v = (k < CC) ? w_ih1[(size_t)R * CC + k] : 0.0f;
        __half h = __float2half_rn(v);
        g_w1b[0][n] = p ? __float2half_rn(v - __half2float(h)) : h;
    }
    grid_sync();

    const int gt   = *gtp;
    const int cond = *condp;
    int period = gt + cond;
    if (period < 1) period = 1;

    int gidx = 0;

    #pragma unroll 1
    for (int ts = 0; ts < TT; ts++) {
        const int rd = ts & 1, wr = rd ^ 1;
        const bool use_gt = (ts % period) < gt;
        const __half* X = use_gt ? g_seqA[ts] : g_xA;

        float acc[2][4][4];

        // ---- Layer 1 (2 + 8 K128 slots) ----
        #pragma unroll
        for (int i = 0; i < 2; i++)
            #pragma unroll
            for (int j = 0; j < 4; j++)
                #pragma unroll
                for (int k = 0; k < 4; k++) acc[i][j][k] = 0.0f;
        gemm2(X, g_w1b[blk], 2, g_hA[0][rd], g_wb[0][blk], 8,
              smbase, acc, oa, ob, gidx);
        layer_finish(acc, sbias + 0, cbase + 0, g_hA[0][wr], (float*)0,
                     scratch);
        grid_sync();

        // ---- Layer 2 (8 + 8) ----
        #pragma unroll
        for (int i = 0; i < 2; i++)
            #pragma unroll
            for (int j = 0; j < 4; j++)
                #pragma unroll
                for (int k = 0; k < 4; k++) acc[i][j][k] = 0.0f;
        gemm2(g_hA[0][wr], g_wb[1][blk], 8, g_hA[1][rd], g_wb[2][blk], 8,
              smbase, acc, oa, ob, gidx);
        layer_finish(acc, sbias + 32, cbase + 1024, g_hA[1][wr], (float*)0,
                     scratch);
        grid_sync();

        // ---- Layer 3 (8 + 8) ----
        #pragma unroll
        for (int i = 0; i < 2; i++)
            #pragma unroll
            for (int j = 0; j < 4; j++)
                #pragma unroll
                for (int k = 0; k < 4; k++) acc[i][j][k] = 0.0f;
        gemm2(g_hA[1][wr], g_wb[3][blk], 8, g_hA[2][rd], g_wb[4][blk], 8,
              smbase, acc, oa, ob, gidx);
        layer_finish(acc, sbias + 64, cbase + 2048, g_hA[2][wr], g_h3,
                     scratch);
        grid_sync();

        // ---- Decoder ----
        decoder_phase(g_h3, dec_w, dec_b, out + (size_t)ts * CC, sH);
        // tail sync only needed if next step reads g_xA (self-fed)
        if ((ts + 1 < TT) && (((ts + 1) % period) >= gt)) grid_sync();
    }
}

// ---------------------------------------------------------------------------
extern "C" void kernel_launch(void* const* d_in, const int* in_sizes, int n_in,
                              void* d_out, int out_size)
{
    (void)in_sizes; (void)n_in; (void)out_size;
    cudaFuncSetAttribute(aclstm_kernel,
                         cudaFuncAttributeMaxDynamicSharedMemorySize,
                         SMEM_BYTES);
    aclstm_kernel<<<NBLK, NTHR, SMEM_BYTES>>>(
        (const float*)d_in[0],
        (const float*)d_in[1],  (const float*)d_in[2],
        (const float*)d_in[3],  (const float*)d_in[4],
        (const float*)d_in[5],  (const float*)d_in[6],
        (const float*)d_in[7],  (const float*)d_in[8],
        (const float*)d_in[9],  (const float*)d_in[10],
        (const float*)d_in[11], (const float*)d_in[12],
        (const float*)d_in[13], (const float*)d_in[14],
        (const int*)d_in[15],   (const int*)d_in[16],
        (float*)d_out);
}

// round 16
// speedup vs baseline: 3.9006x; 1.0619x over previous
#include <cuda_runtime.h>
#include <cuda_fp16.h>
#include <math.h>
#include <stdint.h>

#define BB   128
#define TT   256
#define HH   1024
#define CC   171
#define NBLK 128
#define NTHR 512
#define SH_LD 1028

#define HCH  16384            // halves per K64 A chunk (2 planes x 128 x 64)
#define HLAY (16 * HCH)
#define WCH  4096             // halves per K64 W chunk (2 planes x 32 x 64)

#define NSTG 2
#define STAGE_BYTES 81920     // K128 slot: A 65536 + B 16384
#define SM_SCR   (NSTG * STAGE_BYTES)   // 163840: scratch(50688) U decoder(32896)
#define SCR_BYTES 50688                 // 12 warps x 32 lanes x 33 floats
#define SM_MBAR  (SM_SCR + SCR_BYTES)   // 214528
#define MB_FULL  (SM_MBAR)              // 2 x 8B
#define MB_EMPTY (SM_MBAR + 16)         // 2 x 8B
#define SM_BIAS  (SM_MBAR + 64)         // 96 floats
#define SM_C     (SM_BIAS + 384)        // 3 x 1024 floats
#define SMEM_BYTES (SM_C + 12288)       // 227264 B

// ---------------- persistent state (module statics, no runtime alloc) ------
__device__ __align__(16) __half g_hA[3][2][HLAY];      // pre-swizzled h chunks
__device__ __align__(16) __half g_xA[4 * HCH];         // self-fed frame (padded)
__device__ __align__(16) __half g_seqA[TT][4 * HCH];   // pre-split seq (padded)
__device__ __align__(16) __half g_wb[5][NBLK][16 * WCH];
__device__ __align__(16) __half g_w1b[NBLK][4 * WCH];
__device__ float g_h3[BB * HH];
__device__ int g_ph[4 * TT + 8];        // per-phase arrival counters
__device__ unsigned long long g_arrive; // init-barrier only
__device__ unsigned long long g_release;

// ---------------- full grid barrier (init only) -----------------------------
__device__ __forceinline__ void grid_sync() {
    __threadfence();
    __syncthreads();
    if (threadIdx.x == 0) {
        unsigned long long a = atomicAdd(&g_arrive, 1ull) + 1ull;
        if ((a % (unsigned long long)NBLK) == 0ull) {
            __threadfence();
            *(volatile unsigned long long*)&g_release = a;
        } else {
            unsigned long long target =
                ((a + (unsigned long long)NBLK - 1ull) / (unsigned long long)NBLK)
                * (unsigned long long)NBLK;
            while (*(volatile unsigned long long*)&g_release < target) { }
            __threadfence();
        }
    }
    __syncthreads();
}

// ---------------- per-phase wait (caller thread only) -----------------------
__device__ __forceinline__ void waitcnt(int p) {
    if (p >= 0) {
        while (((volatile int*)g_ph)[p] < NBLK) { }
        __threadfence();
    }
}

__device__ __forceinline__ float sigf(float x) {
    return 1.0f / (1.0f + __expf(-x));
}
__device__ __forceinline__ float tanhfast(float x) {
    return 1.0f - 2.0f / (__expf(2.0f * x) + 1.0f);
}

// ---------------- mbarrier / bulk-copy helpers -----------------------------
__device__ __forceinline__ void mbar_init(uint32_t mbar, uint32_t count) {
    asm volatile("mbarrier.init.shared.b64 [%0], %1;"
                 :: "r"(mbar), "r"(count) : "memory");
}
__device__ __forceinline__ void mbar_arrive(uint32_t mbar) {
    asm volatile("mbarrier.arrive.shared.b64 _, [%0];"
                 :: "r"(mbar) : "memory");
}
__device__ __forceinline__ void mbar_expect(uint32_t mbar, uint32_t tx) {
    asm volatile("mbarrier.arrive.expect_tx.shared.b64 _, [%0], %1;"
                 :: "r"(mbar), "r"(tx) : "memory");
}
__device__ __forceinline__ void mbar_wait(uint32_t mbar, uint32_t parity) {
    asm volatile(
        "{\n\t.reg .pred P;\n\t"
        "WL%=:\n\t"
        "mbarrier.try_wait.parity.shared::cta.b64 P, [%0], %1;\n\t"
        "@!P bra WL%=;\n\t}"
        :: "r"(mbar), "r"(parity) : "memory");
}
__device__ __forceinline__ void bulkcp(uint32_t dst, const void* src,
                                       uint32_t bytes, uint32_t mbar) {
    asm volatile(
        "cp.async.bulk.shared::cluster.global.mbarrier::complete_tx::bytes "
        "[%0], [%1], %2, [%3];"
        :: "r"(dst), "l"(src), "r"(bytes), "r"(mbar) : "memory");
}

// ---------------- fragment ops ----------------------------------------------
__device__ __forceinline__ void ldsm4(uint32_t a, uint32_t& r0, uint32_t& r1,
                                      uint32_t& r2, uint32_t& r3) {
    asm volatile("ldmatrix.sync.aligned.m8n8.x4.shared.b16 {%0,%1,%2,%3}, [%4];"
                 : "=r"(r0), "=r"(r1), "=r"(r2), "=r"(r3) : "r"(a));
}
__device__ __forceinline__ void mma16(float* d,
    uint32_t a0, uint32_t a1, uint32_t a2, uint32_t a3,
    uint32_t b0, uint32_t b1)
{
    asm volatile(
        "mma.sync.aligned.m16n8k16.row.col.f32.f16.f16.f32 "
        "{%0,%1,%2,%3}, {%4,%5,%6,%7}, {%8,%9}, {%0,%1,%2,%3};\n"
        : "+f"(d[0]), "+f"(d[1]), "+f"(d[2]), "+f"(d[3])
        : "r"(a0), "r"(a1), "r"(a2), "r"(a3), "r"(b0), "r"(b1));
}

// ---------------------------------------------------------------------------
// Compute one K64 sub-chunk. Warp wrp: mg = wrp&3 -> rows 32*mg..+31;
// kq = wrp>>2 -> k16 quarter. Tile per warp: m32 x n32 x k16.
// ---------------------------------------------------------------------------
__device__ __forceinline__ void compute_sub(uint32_t aB, uint32_t bB,
    const uint32_t (&oa)[2][2], const uint32_t (&ob)[2][2],
    float (&acc)[2][4][4])
{
    uint32_t Ah[8], Al[8], Bh[8], Bl[8];
    ldsm4(aB + oa[0][0], Ah[0], Ah[1], Ah[2], Ah[3]);
    ldsm4(aB + oa[0][1], Ah[4], Ah[5], Ah[6], Ah[7]);
    ldsm4(aB + oa[1][0], Al[0], Al[1], Al[2], Al[3]);
    ldsm4(aB + oa[1][1], Al[4], Al[5], Al[6], Al[7]);
    ldsm4(bB + ob[0][0], Bh[0], Bh[1], Bh[2], Bh[3]);
    ldsm4(bB + ob[0][1], Bh[4], Bh[5], Bh[6], Bh[7]);
    ldsm4(bB + ob[1][0], Bl[0], Bl[1], Bl[2], Bl[3]);
    ldsm4(bB + ob[1][1], Bl[4], Bl[5], Bl[6], Bl[7]);
    #pragma unroll
    for (int mf = 0; mf < 2; mf++) {
        #pragma unroll
        for (int nt = 0; nt < 4; nt++) {
            float* d = acc[mf][nt];
            mma16(d, Ah[4*mf+0], Ah[4*mf+1], Ah[4*mf+2], Ah[4*mf+3],
                  Bh[2*nt], Bh[2*nt+1]);
            mma16(d, Al[4*mf+0], Al[4*mf+1], Al[4*mf+2], Al[4*mf+3],
                  Bh[2*nt], Bh[2*nt+1]);
            mma16(d, Ah[4*mf+0], Ah[4*mf+1], Ah[4*mf+2], Ah[4*mf+3],
                  Bl[2*nt], Bl[2*nt+1]);
        }
    }
}

// ---------------------------------------------------------------------------
// Ring-pipelined GEMM: segment 0 (hh, no dependency) then segment 1 (ih).
// Producer (t==0) waits phase `wph` just before filling the first ih slot;
// compute warps keep crunching hh slots meanwhile.
// ---------------------------------------------------------------------------
__device__ __forceinline__ void gemm2(
    const __half* __restrict__ A0s, const __half* __restrict__ W0s, int n0,
    const __half* __restrict__ A1s, const __half* __restrict__ W1s, int n1,
    int wph, uint32_t smbase, float (&acc)[2][4][4],
    const uint32_t (&oa)[2][2], const uint32_t (&ob)[2][2], int& gidx)
{
    const int t = threadIdx.x;
    const int ntot = n0 + n1;
    const uint32_t mbF = smbase + MB_FULL;
    const uint32_t mbE = smbase + MB_EMPTY;

    if (t == 0) {   // prefetch slot for first (hh) chunk — needs no gate
        int idx = gidx, s = idx & 1;
        mbar_wait(mbE + 8 * s, (uint32_t)((idx >> 1) & 1));
        mbar_expect(mbF + 8 * s, STAGE_BYTES);
        uint32_t dst = smbase + s * STAGE_BYTES;
        bulkcp(dst, A0s, 65536, mbF + 8 * s);
        bulkcp(dst + 65536, W0s, 16384, mbF + 8 * s);
    }
    #pragma unroll 1
    for (int i = 0; i < ntot; i++) {
        int idx = gidx + i, s = idx & 1;
        mbar_wait(mbF + 8 * s, (uint32_t)((idx >> 1) & 1));
        if (t == 0 && i + 1 < ntot) {
            int j = i + 1, idx2 = gidx + j, s2 = idx2 & 1;
            if (j == n0) waitcnt(wph);   // dependency gate, producer only
            mbar_wait(mbE + 8 * s2, (uint32_t)((idx2 >> 1) & 1));
            mbar_expect(mbF + 8 * s2, STAGE_BYTES);
            uint32_t dst = smbase + s2 * STAGE_BYTES;
            const __half* A = (j < n0) ? A0s : A1s;
            const __half* W = (j < n0) ? W0s : W1s;
            int jj = (j < n0) ? j : j - n0;
            bulkcp(dst, A + (size_t)jj * (2 * HCH), 65536, mbF + 8 * s2);
            bulkcp(dst + 65536, W + (size_t)jj * (2 * WCH), 16384,
                   mbF + 8 * s2);
        }
        uint32_t slot = smbase + s * STAGE_BYTES;
        compute_sub(slot,         slot + 65536, oa, ob, acc);
        compute_sub(slot + 32768, slot + 73728, oa, ob, acc);
        __syncwarp();
        if ((t & 31) == 0) mbar_arrive(mbE + 8 * s);
    }
    gidx += ntot;
}

// ---------------------------------------------------------------------------
// 4-way k-quarter reduction + thread-local LSTM epilogue (c-state in smem).
// Scratch stride 33 floats (>= 32-float payload, conflict-free).
// Ends with threadfence + syncthreads so the caller can arrive immediately.
// ---------------------------------------------------------------------------
__device__ __forceinline__ void layer_finish(
    float (&acc)[2][4][4], const float* __restrict__ sb,
    float* __restrict__ cmem, __half* __restrict__ hdst,
    float* __restrict__ hf, float* __restrict__ scratch)
{
    const int lane = threadIdx.x & 31;
    const int wrp  = threadIdx.x >> 5;
    const int mg = wrp & 3, kq = wrp >> 2;
    if (kq > 0) {
        float* p = scratch + (size_t)(((kq - 1) * 4 + mg) * 32 + lane) * 33;
        #pragma unroll
        for (int mf = 0; mf < 2; mf++)
            #pragma unroll
            for (int nt = 0; nt < 4; nt++)
                #pragma unroll
                for (int ii = 0; ii < 4; ii++)
                    p[mf * 16 + nt * 4 + ii] = acc[mf][nt][ii];
    }
    __syncthreads();
    if (kq == 0) {
        #pragma unroll
        for (int q = 0; q < 3; q++) {
            const float* p = scratch + (size_t)((q * 4 + mg) * 32 + lane) * 33;
            #pragma unroll
            for (int mf = 0; mf < 2; mf++)
                #pragma unroll
                for (int nt = 0; nt < 4; nt++)
                    #pragma unroll
                    for (int ii = 0; ii < 4; ii++)
                        acc[mf][nt][ii] += p[mf * 16 + nt * 4 + ii];
        }
        const int tt  = threadIdx.x;   // < 128 here
        const int cu  = blockIdx.x >> 3;
        const int cg7 = blockIdx.x & 7;
        const int u0  = blockIdx.x * 8;
        const int du0 = (lane & 3) * 2;
        #pragma unroll
        for (int mf = 0; mf < 2; mf++) {
            #pragma unroll
            for (int rh = 0; rh < 2; rh++) {
                const int R = mg * 32 + mf * 16 + rh * 8 + (lane >> 2);
                float hv[2];
                #pragma unroll
                for (int p = 0; p < 2; p++) {
                    const int idx = rh * 2 + p;
                    const int ci  = mf * 4 + rh * 2 + p;
                    float zi = acc[mf][0][idx] + sb[0  + du0 + p];
                    float zf = acc[mf][1][idx] + sb[8  + du0 + p];
                    float zg = acc[mf][2][idx] + sb[16 + du0 + p];
                    float zo = acc[mf][3][idx] + sb[24 + du0 + p];
                    float co = cmem[ci * 128 + tt];
                    float cn = sigf(zf) * co + sigf(zi) * tanhfast(zg);
                    cmem[ci * 128 + tt] = cn;
                    hv[p] = sigf(zo) * tanhfast(cn);
                }
                const int o = cu * HCH + R * 64 + ((cg7 ^ (R & 7)) << 3) + du0;
                __half a0 = __float2half_rn(hv[0]);
                __half a1 = __float2half_rn(hv[1]);
                *(__half2*)(hdst + o) = __halves2half2(a0, a1);
                *(__half2*)(hdst + 8192 + o) = __halves2half2(
                    __float2half_rn(hv[0] - __half2float(a0)),
                    __float2half_rn(hv[1] - __half2float(a1)));
                if (hf)
                    *(float2*)(hf + (size_t)R * HH + u0 + du0) =
                        make_float2(hv[0], hv[1]);
            }
        }
    }
    __threadfence();
    __syncthreads();
}

// Decoder: waits phase phL3 (block-wide), computes, arrives phase phD.
__device__ __forceinline__ void decoder_phase(
    const float* __restrict__ h3,
    const float* __restrict__ dw, const float* __restrict__ db,
    float* __restrict__ outt, float* __restrict__ sH, int phL3, int phD)
{
    const int t   = threadIdx.x;
    const int bg  = blockIdx.x >> 3;
    const int cg  = blockIdx.x & 7;
    const int rb0 = bg * 8;
    const int cc0 = cg * 22;
    if (t == 0) waitcnt(phL3);
    __syncthreads();
    for (int e = t; e < 8 * HH; e += NTHR) {
        int r = e >> 10, k = e & (HH - 1);
        sH[r * SH_LD + k] = h3[(rb0 + r) * HH + k];
    }
    __syncthreads();
    if (t < 352) {
        const int idx = t >> 1, p = t & 1;
        const int br = idx / 22, cc = idx % 22;
        const int c  = cc0 + cc;
        float s = 0.0f;
        if (c < CC) {
            const float4* wr = (const float4*)(dw + (size_t)c * HH) + p * 128;
            const float4* hr = (const float4*)(sH + br * SH_LD) + p * 128;
            #pragma unroll 4
            for (int k4 = 0; k4 < 128; k4++) {
                float4 w = wr[k4];
                float4 h = hr[k4];
                s += w.x * h.x + w.y * h.y + w.z * h.z + w.w * h.w;
            }
        }
        s += __shfl_xor_sync(0xFFFFFFFFu, s, 1);
        if (p == 0 && c < CC) {
            float o = s + db[c];
            const int b = rb0 + br;
            outt[(size_t)b * (size_t)(TT * CC) + c] = o;
            const int ch = c >> 6, c6 = c & 63;
            const int pos = (((c6 >> 3) ^ (b & 7)) << 3) | (c6 & 7);
            __half s0 = __float2half_rn(o);
            g_xA[ch * HCH + b * 64 + pos] = s0;
            g_xA[ch * HCH + 8192 + b * 64 + pos] =
                __float2half_rn(o - __half2float(s0));
        }
    }
    __threadfence();
    __syncthreads();
    if (t == 0) atomicAdd(&g_ph[phD], 1);
}

// ---------------------------------------------------------------------------
__global__ void __launch_bounds__(NTHR, 1) aclstm_kernel(
    const float* __restrict__ seq,
    const float* __restrict__ w_ih1, const float* __restrict__ w_hh1,
    const float* __restrict__ b_ih1, const float* __restrict__ b_hh1,
    const float* __restrict__ w_ih2, const float* __restrict__ w_hh2,
    const float* __restrict__ b_ih2, const float* __restrict__ b_hh2,
    const float* __restrict__ w_ih3, const float* __restrict__ w_hh3,
    const float* __restrict__ b_ih3, const float* __restrict__ b_hh3,
    const float* __restrict__ dec_w, const float* __restrict__ dec_b,
    const int* __restrict__ gtp, const int* __restrict__ condp,
    float* __restrict__ out)
{
    extern __shared__ __align__(1024) unsigned char dynsm[];
    const uint32_t smbase = (uint32_t)__cvta_generic_to_shared(dynsm);
    float* sH      = (float*)(dynsm + SM_SCR);
    float* scratch = (float*)(dynsm + SM_SCR);
    const float* sbias = (const float*)(dynsm + SM_BIAS);
    float* cbase = (float*)(dynsm + SM_C);
    const int t   = threadIdx.x;
    const int blk = blockIdx.x;
    const int u0  = blk * 8;
    const long gtid = (long)blk * NTHR + t;
    const long gstr = (long)NBLK * NTHR;

    // ---- mbarrier init + bias staging + c zero ----
    if (t == 0) {
        #pragma unroll
        for (int s = 0; s < NSTG; s++) {
            mbar_init(smbase + MB_FULL + 8 * s, 1);
            mbar_init(smbase + MB_EMPTY + 8 * s, 16);
        }
        asm volatile("fence.proxy.async.shared::cta;" ::: "memory");
    }
    if (t < 96) {
        int l = t >> 5, gate = (t & 31) >> 3, du = t & 7;
        const float* bi = (l == 0) ? b_ih1 : (l == 1) ? b_ih2 : b_ih3;
        const float* bh = (l == 0) ? b_hh1 : (l == 1) ? b_hh2 : b_hh3;
        ((float*)(dynsm + SM_BIAS))[t] =
            bi[gate * HH + u0 + du] + bh[gate * HH + u0 + du];
    }
    if (t < 128) {
        #pragma unroll
        for (int i = 0; i < 24; i++) cbase[i * 128 + t] = 0.0f;
    }
    __syncthreads();
    if ((t & 31) == 0) {
        #pragma unroll
        for (int s = 0; s < NSTG; s++) mbar_arrive(smbase + MB_EMPTY + 8 * s);
    }
    __syncthreads();

    // ---- per-thread fragment byte offsets (relative to A/B region bases) ----
    const int lane = t & 31, wrp = t >> 5;
    const int mg = wrp & 3, kq = wrp >> 2;
    const int mat = lane >> 3, rr = lane & 7;
    uint32_t oa[2][2], ob[2][2];
    #pragma unroll
    for (int mf = 0; mf < 2; mf++) {
        int R  = mg * 32 + mf * 16 + ((mat & 1) << 3) + rr;
        int kg = kq * 2 + (mat >> 1);
        uint32_t base = (uint32_t)(R * 128 + ((kg ^ (R & 7)) << 4));
        oa[0][mf] = base;
        oa[1][mf] = base + 16384;
    }
    #pragma unroll
    for (int ntp = 0; ntp < 2; ntp++) {
        int nt = ntp * 2 + (mat >> 1);
        int kg = kq * 2 + (mat & 1);
        int n  = nt * 8 + rr;
        uint32_t base = (uint32_t)(n * 128 + ((kg ^ (n & 7)) << 4));
        ob[0][ntp] = base;
        ob[1][ntp] = base + 4096;
    }

    // ---- init: zero h/x/phases, pre-split seq, re-layout+split weights ----
    for (long e = gtid; e < 4 * TT + 8; e += gstr) g_ph[e] = 0;
    for (long e = gtid; e < HLAY; e += gstr) {
        #pragma unroll
        for (int l = 0; l < 3; l++) g_hA[l][0][e] = __ushort_as_half(0);
    }
    for (long e = gtid; e < 4 * HCH; e += gstr)
        g_xA[e] = __ushort_as_half(0);
    for (long n = gtid; n < (long)TT * 4 * HCH; n += gstr) {
        int tt = (int)(n / (4 * HCH));
        int r  = (int)(n % (4 * HCH));
        int ch = r / HCH; int r2 = r % HCH;
        int p  = r2 >> 13;
        int r3 = r2 & 8191;
        int b  = r3 >> 6;
        int pos = r3 & 63;
        int c  = ch * 64 + (((pos >> 3) ^ (b & 7)) << 3) + (pos & 7);
        float v = (c < CC) ? seq[((size_t)b * TT + tt) * CC + c] : 0.0f;
        __half h = __float2half_rn(v);
        g_seqA[tt][r] = p ? __float2half_rn(v - __half2float(h)) : h;
    }
    for (long n = gtid; n < 5L * NBLK * 16 * WCH; n += gstr) {
        int m   = (int)(n / ((long)NBLK * 16 * WCH));
        long r  = n % ((long)NBLK * 16 * WCH);
        int bl  = (int)(r / (16 * WCH));
        int r2  = (int)(r % (16 * WCH));
        int ch  = r2 / WCH;
        int r3  = r2 % WCH;
        int p   = r3 >> 11;
        int nl  = (r3 >> 6) & 31;
        int pos = r3 & 63;
        int kk  = (((pos >> 3) ^ (nl & 7)) << 3) + (pos & 7);
        int k   = ch * 64 + kk;
        int R   = (nl >> 3) * HH + bl * 8 + (nl & 7);
        const float* Wm = (m == 0) ? w_hh1 : (m == 1) ? w_ih2 :
                          (m == 2) ? w_hh2 : (m == 3) ? w_ih3 : w_hh3;
        float v = Wm[(size_t)R * HH + k];
        __half h = __float2half_rn(v);
        g_wb[0][0][n] = p ? __float2half_rn(v - __half2float(h)) : h;
    }
    for (long n = gtid; n < (long)NBLK * 4 * WCH; n += gstr) {
        int bl  = (int)(n / (4 * WCH));
        int r2  = (int)(n % (4 * WCH));
        int ch  = r2 / WCH;
        int r3  = r2 % WCH;
        int p   = r3 >> 11;
        int nl  = (r3 >> 6) & 31;
        int pos = r3 & 63;
        int kk  = (((pos >> 3) ^ (nl & 7)) << 3) + (pos & 7);
        int k   = ch * 64 + kk;
        int R   = (nl >> 3) * HH + bl * 8 + (nl & 7);
        float v = (k < CC) ? w_ih1[(size_t)R * CC + k] : 0.0f;
        __half h = __float2half_rn(v);
        g_w1b[0][n] = p ? __float2half_rn(v - __half2float(h)) : h;
    }
    grid_sync();

    const int gt   = *gtp;
    const int cond = *condp;
    int period = gt + cond;
    if (period < 1) period = 1;

    int gidx = 0;

    #pragma unroll 1
    for (int ts = 0; ts < TT; ts++) {
        const int rd = ts & 1, wr = rd ^ 1;
        const bool use_gt = (ts % period) < gt;
        const __half* X = use_gt ? g_seqA[ts] : g_xA;
        const int phb = ts * 4;

        float acc[2][4][4];

        // ---- Layer 1: hh (8 slots) then x (2 slots) ----
        #pragma unroll
        for (int i = 0; i < 2; i++)
            #pragma unroll
            for (int j = 0; j < 4; j++)
                #pragma unroll
                for (int k = 0; k < 4; k++) acc[i][j][k] = 0.0f;
        gemm2(g_hA[0][rd], g_wb[0][blk], 8, X, g_w1b[blk], 2,
              (!use_gt && ts > 0) ? (phb - 1) : -1,
              smbase, acc, oa, ob, gidx);
        layer_finish(acc, sbias + 0, cbase + 0, g_hA[0][wr], (float*)0,
                     scratch);
        if (t == 0) atomicAdd(&g_ph[phb + 0], 1);

        // ---- Layer 2: hh then ih ----
        #pragma unroll
        for (int i = 0; i < 2; i++)
            #pragma unroll
            for (int j = 0; j < 4; j++)
                #pragma unroll
                for (int k = 0; k < 4; k++) acc[i][j][k] = 0.0f;
        gemm2(g_hA[1][rd], g_wb[2][blk], 8, g_hA[0][wr], g_wb[1][blk], 8,
              phb + 0, smbase, acc, oa, ob, gidx);
        layer_finish(acc, sbias + 32, cbase + 1024, g_hA[1][wr], (float*)0,
                     scratch);
        if (t == 0) atomicAdd(&g_ph[phb + 1], 1);

        // ---- Layer 3: hh then ih ----
        #pragma unroll
        for (int i = 0; i < 2; i++)
            #pragma unroll
            for (int j = 0; j < 4; j++)
                #pragma unroll
                for (int k = 0; k < 4; k++) acc[i][j][k] = 0.0f;
        gemm2(g_hA[2][rd], g_wb[4][blk], 8, g_hA[1][wr], g_wb[3][blk], 8,
              phb + 1, smbase, acc, oa, ob, gidx);
        layer_finish(acc, sbias + 64, cbase + 2048, g_hA[2][wr], g_h3,
                     scratch);
        if (t == 0) atomicAdd(&g_ph[phb + 2], 1);

        // ---- Decoder (block-wide wait on L3 phase; arrives D phase) ----
        decoder_phase(g_h3, dec_w, dec_b, out + (size_t)ts * CC, sH,
                      phb + 2, phb + 3);
    }
}

// ---------------------------------------------------------------------------
extern "C" void kernel_launch(void* const* d_in, const int* in_sizes, int n_in,
                              void* d_out, int out_size)
{
    (void)in_sizes; (void)n_in; (void)out_size;
    cudaFuncSetAttribute(aclstm_kernel,
                         cudaFuncAttributeMaxDynamicSharedMemorySize,
                         SMEM_BYTES);
    aclstm_kernel<<<NBLK, NTHR, SMEM_BYTES>>>(
        (const float*)d_in[0],
        (const float*)d_in[1],  (const float*)d_in[2],
        (const float*)d_in[3],  (const float*)d_in[4],
        (const float*)d_in[5],  (const float*)d_in[6],
        (const float*)d_in[7],  (const float*)d_in[8],
        (const float*)d_in[9],  (const float*)d_in[10],
        (const float*)d_in[11], (const float*)d_in[12],
        (const float*)d_in[13], (const float*)d_in[14],
        (const int*)d_in[15],   (const int*)d_in[16],
        (float*)d_out);
}

// round 17
// speedup vs baseline: 3.9197x; 1.0049x over previous
#include <cuda_runtime.h>
#include <cuda_fp16.h>
#include <math.h>
#include <stdint.h>

#define BB   128
#define TT   256
#define HH   1024
#define CC   171
#define NBLK 128
#define NTHR 512
#define SH_LD 1028

#define HCH  16384            // halves per K64 A chunk (2 planes x 128 x 64)
#define HLAY (16 * HCH)
#define WCH  4096             // halves per K64 W chunk (2 planes x 32 x 64)

#define NSTG 2
#define STAGE_BYTES 81920     // K128 slot: A 65536 + B 16384
#define SM_SCR   (NSTG * STAGE_BYTES)   // 163840: scratch(50688) U decoder(32896)
#define SCR_BYTES 50688                 // 12 warps x 32 lanes x 33 floats
#define SM_MBAR  (SM_SCR + SCR_BYTES)   // 214528
#define MB_FULL  (SM_MBAR)              // 2 x 8B
#define MB_EMPTY (SM_MBAR + 16)         // 2 x 8B
#define SM_BIAS  (SM_MBAR + 64)         // 96 floats
#define SM_C     (SM_BIAS + 384)        // 3 x 1024 floats
#define SMEM_BYTES (SM_C + 12288)       // 227264 B

// ---------------- persistent state (module statics, no runtime alloc) ------
__device__ __align__(16) __half g_hA[3][2][HLAY];      // pre-swizzled h chunks
__device__ __align__(16) __half g_xA[4 * HCH];         // self-fed frame (padded)
__device__ __align__(16) __half g_seqA[TT][4 * HCH];   // pre-split seq (padded)
__device__ __align__(16) __half g_wb[5][NBLK][16 * WCH];
__device__ __align__(16) __half g_w1b[NBLK][4 * WCH];
__device__ float g_h3[BB * HH];
__device__ int g_ph[4 * TT + 8];        // per-phase arrival counters
__device__ unsigned long long g_arrive; // init-barrier only
__device__ unsigned long long g_release;

// ---------------- full grid barrier (init only) -----------------------------
__device__ __forceinline__ void grid_sync() {
    __threadfence();
    __syncthreads();
    if (threadIdx.x == 0) {
        unsigned long long a = atomicAdd(&g_arrive, 1ull) + 1ull;
        if ((a % (unsigned long long)NBLK) == 0ull) {
            __threadfence();
            *(volatile unsigned long long*)&g_release = a;
        } else {
            unsigned long long target =
                ((a + (unsigned long long)NBLK - 1ull) / (unsigned long long)NBLK)
                * (unsigned long long)NBLK;
            while (*(volatile unsigned long long*)&g_release < target) { }
            __threadfence();
        }
    }
    __syncthreads();
}

// ---------------- per-phase wait (caller thread only) -----------------------
__device__ __forceinline__ void waitcnt(int p) {
    if (p >= 0) {
        while (((volatile int*)g_ph)[p] < NBLK) { }
        __threadfence();
    }
}

__device__ __forceinline__ float sigf(float x) {
    return 1.0f / (1.0f + __expf(-x));
}
__device__ __forceinline__ float tanhfast(float x) {
    return 1.0f - 2.0f / (__expf(2.0f * x) + 1.0f);
}

// ---------------- mbarrier / bulk-copy helpers -----------------------------
__device__ __forceinline__ void mbar_init(uint32_t mbar, uint32_t count) {
    asm volatile("mbarrier.init.shared.b64 [%0], %1;"
                 :: "r"(mbar), "r"(count) : "memory");
}
__device__ __forceinline__ void mbar_arrive(uint32_t mbar) {
    asm volatile("mbarrier.arrive.shared.b64 _, [%0];"
                 :: "r"(mbar) : "memory");
}
__device__ __forceinline__ void mbar_expect(uint32_t mbar, uint32_t tx) {
    asm volatile("mbarrier.arrive.expect_tx.shared.b64 _, [%0], %1;"
                 :: "r"(mbar), "r"(tx) : "memory");
}
__device__ __forceinline__ void mbar_wait(uint32_t mbar, uint32_t parity) {
    asm volatile(
        "{\n\t.reg .pred P;\n\t"
        "WL%=:\n\t"
        "mbarrier.try_wait.parity.shared::cta.b64 P, [%0], %1;\n\t"
        "@!P bra WL%=;\n\t}"
        :: "r"(mbar), "r"(parity) : "memory");
}
__device__ __forceinline__ void bulkcp(uint32_t dst, const void* src,
                                       uint32_t bytes, uint32_t mbar) {
    asm volatile(
        "cp.async.bulk.shared::cluster.global.mbarrier::complete_tx::bytes "
        "[%0], [%1], %2, [%3];"
        :: "r"(dst), "l"(src), "r"(bytes), "r"(mbar) : "memory");
}

// ---------------- fragment ops ----------------------------------------------
__device__ __forceinline__ void ldsm4(uint32_t a, uint32_t& r0, uint32_t& r1,
                                      uint32_t& r2, uint32_t& r3) {
    asm volatile("ldmatrix.sync.aligned.m8n8.x4.shared.b16 {%0,%1,%2,%3}, [%4];"
                 : "=r"(r0), "=r"(r1), "=r"(r2), "=r"(r3) : "r"(a));
}
__device__ __forceinline__ void mma16(float* d,
    uint32_t a0, uint32_t a1, uint32_t a2, uint32_t a3,
    uint32_t b0, uint32_t b1)
{
    asm volatile(
        "mma.sync.aligned.m16n8k16.row.col.f32.f16.f16.f32 "
        "{%0,%1,%2,%3}, {%4,%5,%6,%7}, {%8,%9}, {%0,%1,%2,%3};\n"
        : "+f"(d[0]), "+f"(d[1]), "+f"(d[2]), "+f"(d[3])
        : "r"(a0), "r"(a1), "r"(a2), "r"(a3), "r"(b0), "r"(b1));
}

// ---------------------------------------------------------------------------
// Compute one K64 sub-chunk. Warp wrp: mg = wrp&3 -> rows 32*mg..+31;
// kq = wrp>>2 -> k16 quarter. Tile per warp: m32 x n32 x k16.
// ---------------------------------------------------------------------------
__device__ __forceinline__ void compute_sub(uint32_t aB, uint32_t bB,
    const uint32_t (&oa)[2][2], const uint32_t (&ob)[2][2],
    float (&acc)[2][4][4])
{
    uint32_t Ah[8], Al[8], Bh[8], Bl[8];
    ldsm4(aB + oa[0][0], Ah[0], Ah[1], Ah[2], Ah[3]);
    ldsm4(aB + oa[0][1], Ah[4], Ah[5], Ah[6], Ah[7]);
    ldsm4(aB + oa[1][0], Al[0], Al[1], Al[2], Al[3]);
    ldsm4(aB + oa[1][1], Al[4], Al[5], Al[6], Al[7]);
    ldsm4(bB + ob[0][0], Bh[0], Bh[1], Bh[2], Bh[3]);
    ldsm4(bB + ob[0][1], Bh[4], Bh[5], Bh[6], Bh[7]);
    ldsm4(bB + ob[1][0], Bl[0], Bl[1], Bl[2], Bl[3]);
    ldsm4(bB + ob[1][1], Bl[4], Bl[5], Bl[6], Bl[7]);
    #pragma unroll
    for (int mf = 0; mf < 2; mf++) {
        #pragma unroll
        for (int nt = 0; nt < 4; nt++) {
            float* d = acc[mf][nt];
            mma16(d, Ah[4*mf+0], Ah[4*mf+1], Ah[4*mf+2], Ah[4*mf+3],
                  Bh[2*nt], Bh[2*nt+1]);
            mma16(d, Al[4*mf+0], Al[4*mf+1], Al[4*mf+2], Al[4*mf+3],
                  Bh[2*nt], Bh[2*nt+1]);
            mma16(d, Ah[4*mf+0], Ah[4*mf+1], Ah[4*mf+2], Ah[4*mf+3],
                  Bl[2*nt], Bl[2*nt+1]);
        }
    }
}

// ---------------------------------------------------------------------------
// Ring-pipelined GEMM with CHAINED producer: while computing the last chunk,
// the producer already fills the NEXT gemm2's first chunk (nA/nW, gated by
// nph). `first` = issue the initial fill here (only the very first call).
// ---------------------------------------------------------------------------
__device__ __forceinline__ void gemm2(
    const __half* __restrict__ A0s, const __half* __restrict__ W0s, int n0,
    const __half* __restrict__ A1s, const __half* __restrict__ W1s, int n1,
    int wph,
    const __half* __restrict__ nA, const __half* __restrict__ nW, int nph,
    bool first, uint32_t smbase, float (&acc)[2][4][4],
    const uint32_t (&oa)[2][2], const uint32_t (&ob)[2][2], int& gidx)
{
    const int t = threadIdx.x;
    const int ntot = n0 + n1;
    const uint32_t mbF = smbase + MB_FULL;
    const uint32_t mbE = smbase + MB_EMPTY;

    if (t == 0 && first) {   // bootstrap fill (very first GEMM only)
        int idx = gidx, s = idx & 1;
        mbar_wait(mbE + 8 * s, (uint32_t)((idx >> 1) & 1));
        mbar_expect(mbF + 8 * s, STAGE_BYTES);
        uint32_t dst = smbase + s * STAGE_BYTES;
        bulkcp(dst, A0s, 65536, mbF + 8 * s);
        bulkcp(dst + 65536, W0s, 16384, mbF + 8 * s);
    }
    #pragma unroll 1
    for (int i = 0; i < ntot; i++) {
        int idx = gidx + i, s = idx & 1;
        mbar_wait(mbF + 8 * s, (uint32_t)((idx >> 1) & 1));
        if (t == 0) {
            int j = i + 1;
            if (j < ntot) {
                int idx2 = gidx + j, s2 = idx2 & 1;
                if (j == n0) waitcnt(wph);   // dependency gate (ih segment)
                mbar_wait(mbE + 8 * s2, (uint32_t)((idx2 >> 1) & 1));
                mbar_expect(mbF + 8 * s2, STAGE_BYTES);
                uint32_t dst = smbase + s2 * STAGE_BYTES;
                const __half* A = (j < n0) ? A0s : A1s;
                const __half* W = (j < n0) ? W0s : W1s;
                int jj = (j < n0) ? j : j - n0;
                bulkcp(dst, A + (size_t)jj * (2 * HCH), 65536, mbF + 8 * s2);
                bulkcp(dst + 65536, W + (size_t)jj * (2 * WCH), 16384,
                       mbF + 8 * s2);
            } else if (nA) {  // chained fill: next gemm2's chunk 0
                int idx2 = gidx + ntot, s2 = idx2 & 1;
                waitcnt(nph);
                mbar_wait(mbE + 8 * s2, (uint32_t)((idx2 >> 1) & 1));
                mbar_expect(mbF + 8 * s2, STAGE_BYTES);
                uint32_t dst = smbase + s2 * STAGE_BYTES;
                bulkcp(dst, nA, 65536, mbF + 8 * s2);
                bulkcp(dst + 65536, nW, 16384, mbF + 8 * s2);
            }
        }
        uint32_t slot = smbase + s * STAGE_BYTES;
        compute_sub(slot,         slot + 65536, oa, ob, acc);
        compute_sub(slot + 32768, slot + 73728, oa, ob, acc);
        __syncwarp();
        if ((t & 31) == 0) mbar_arrive(mbE + 8 * s);
    }
    gidx += ntot;
}

// ---------------------------------------------------------------------------
// 4-way k-quarter reduction + thread-local LSTM epilogue (c-state in smem).
// Scratch stride 33 floats (>= 32-float payload, conflict-free).
// ---------------------------------------------------------------------------
__device__ __forceinline__ void layer_finish(
    float (&acc)[2][4][4], const float* __restrict__ sb,
    float* __restrict__ cmem, __half* __restrict__ hdst,
    float* __restrict__ hf, float* __restrict__ scratch)
{
    const int lane = threadIdx.x & 31;
    const int wrp  = threadIdx.x >> 5;
    const int mg = wrp & 3, kq = wrp >> 2;
    if (kq > 0) {
        float* p = scratch + (size_t)(((kq - 1) * 4 + mg) * 32 + lane) * 33;
        #pragma unroll
        for (int mf = 0; mf < 2; mf++)
            #pragma unroll
            for (int nt = 0; nt < 4; nt++)
                #pragma unroll
                for (int ii = 0; ii < 4; ii++)
                    p[mf * 16 + nt * 4 + ii] = acc[mf][nt][ii];
    }
    __syncthreads();
    if (kq == 0) {
        #pragma unroll
        for (int q = 0; q < 3; q++) {
            const float* p = scratch + (size_t)((q * 4 + mg) * 32 + lane) * 33;
            #pragma unroll
            for (int mf = 0; mf < 2; mf++)
                #pragma unroll
                for (int nt = 0; nt < 4; nt++)
                    #pragma unroll
                    for (int ii = 0; ii < 4; ii++)
                        acc[mf][nt][ii] += p[mf * 16 + nt * 4 + ii];
        }
        const int tt  = threadIdx.x;   // < 128 here
        const int cu  = blockIdx.x >> 3;
        const int cg7 = blockIdx.x & 7;
        const int u0  = blockIdx.x * 8;
        const int du0 = (lane & 3) * 2;
        #pragma unroll
        for (int mf = 0; mf < 2; mf++) {
            #pragma unroll
            for (int rh = 0; rh < 2; rh++) {
                const int R = mg * 32 + mf * 16 + rh * 8 + (lane >> 2);
                float hv[2];
                #pragma unroll
                for (int p = 0; p < 2; p++) {
                    const int idx = rh * 2 + p;
                    const int ci  = mf * 4 + rh * 2 + p;
                    float zi = acc[mf][0][idx] + sb[0  + du0 + p];
                    float zf = acc[mf][1][idx] + sb[8  + du0 + p];
                    float zg = acc[mf][2][idx] + sb[16 + du0 + p];
                    float zo = acc[mf][3][idx] + sb[24 + du0 + p];
                    float co = cmem[ci * 128 + tt];
                    float cn = sigf(zf) * co + sigf(zi) * tanhfast(zg);
                    cmem[ci * 128 + tt] = cn;
                    hv[p] = sigf(zo) * tanhfast(cn);
                }
                const int o = cu * HCH + R * 64 + ((cg7 ^ (R & 7)) << 3) + du0;
                __half a0 = __float2half_rn(hv[0]);
                __half a1 = __float2half_rn(hv[1]);
                *(__half2*)(hdst + o) = __halves2half2(a0, a1);
                *(__half2*)(hdst + 8192 + o) = __halves2half2(
                    __float2half_rn(hv[0] - __half2float(a0)),
                    __float2half_rn(hv[1] - __half2float(a1)));
                if (hf)
                    *(float2*)(hf + (size_t)R * HH + u0 + du0) =
                        make_float2(hv[0], hv[1]);
            }
        }
    }
    __threadfence();
    __syncthreads();
}

// Decoder: waits phase phL3 (block-wide), computes, arrives phase phD.
__device__ __forceinline__ void decoder_phase(
    const float* __restrict__ h3,
    const float* __restrict__ dw, const float* __restrict__ db,
    float* __restrict__ outt, float* __restrict__ sH, int phL3, int phD)
{
    const int t   = threadIdx.x;
    const int bg  = blockIdx.x >> 3;
    const int cg  = blockIdx.x & 7;
    const int rb0 = bg * 8;
    const int cc0 = cg * 22;
    if (t == 0) waitcnt(phL3);
    __syncthreads();
    for (int e = t; e < 8 * HH; e += NTHR) {
        int r = e >> 10, k = e & (HH - 1);
        sH[r * SH_LD + k] = h3[(rb0 + r) * HH + k];
    }
    __syncthreads();
    if (t < 352) {
        const int idx = t >> 1, p = t & 1;
        const int br = idx / 22, cc = idx % 22;
        const int c  = cc0 + cc;
        float s = 0.0f;
        if (c < CC) {
            const float4* wr = (const float4*)(dw + (size_t)c * HH) + p * 128;
            const float4* hr = (const float4*)(sH + br * SH_LD) + p * 128;
            #pragma unroll 4
            for (int k4 = 0; k4 < 128; k4++) {
                float4 w = wr[k4];
                float4 h = hr[k4];
                s += w.x * h.x + w.y * h.y + w.z * h.z + w.w * h.w;
            }
        }
        s += __shfl_xor_sync(0xFFFFFFFFu, s, 1);
        if (p == 0 && c < CC) {
            float o = s + db[c];
            const int b = rb0 + br;
            outt[(size_t)b * (size_t)(TT * CC) + c] = o;
            const int ch = c >> 6, c6 = c & 63;
            const int pos = (((c6 >> 3) ^ (b & 7)) << 3) | (c6 & 7);
            __half s0 = __float2half_rn(o);
            g_xA[ch * HCH + b * 64 + pos] = s0;
            g_xA[ch * HCH + 8192 + b * 64 + pos] =
                __float2half_rn(o - __half2float(s0));
        }
    }
    __threadfence();
    __syncthreads();
    if (t == 0) atomicAdd(&g_ph[phD], 1);
}

// ---------------------------------------------------------------------------
__global__ void __launch_bounds__(NTHR, 1) aclstm_kernel(
    const float* __restrict__ seq,
    const float* __restrict__ w_ih1, const float* __restrict__ w_hh1,
    const float* __restrict__ b_ih1, const float* __restrict__ b_hh1,
    const float* __restrict__ w_ih2, const float* __restrict__ w_hh2,
    const float* __restrict__ b_ih2, const float* __restrict__ b_hh2,
    const float* __restrict__ w_ih3, const float* __restrict__ w_hh3,
    const float* __restrict__ b_ih3, const float* __restrict__ b_hh3,
    const float* __restrict__ dec_w, const float* __restrict__ dec_b,
    const int* __restrict__ gtp, const int* __restrict__ condp,
    float* __restrict__ out)
{
    extern __shared__ __align__(1024) unsigned char dynsm[];
    const uint32_t smbase = (uint32_t)__cvta_generic_to_shared(dynsm);
    float* sH      = (float*)(dynsm + SM_SCR);
    float* scratch = (float*)(dynsm + SM_SCR);
    const float* sbias = (const float*)(dynsm + SM_BIAS);
    float* cbase = (float*)(dynsm + SM_C);
    const int t   = threadIdx.x;
    const int blk = blockIdx.x;
    const int u0  = blk * 8;
    const long gtid = (long)blk * NTHR + t;
    const long gstr = (long)NBLK * NTHR;

    // ---- mbarrier init + bias staging + c zero ----
    if (t == 0) {
        #pragma unroll
        for (int s = 0; s < NSTG; s++) {
            mbar_init(smbase + MB_FULL + 8 * s, 1);
            mbar_init(smbase + MB_EMPTY + 8 * s, 16);
        }
        asm volatile("fence.proxy.async.shared::cta;" ::: "memory");
    }
    if (t < 96) {
        int l = t >> 5, gate = (t & 31) >> 3, du = t & 7;
        const float* bi = (l == 0) ? b_ih1 : (l == 1) ? b_ih2 : b_ih3;
        const float* bh = (l == 0) ? b_hh1 : (l == 1) ? b_hh2 : b_hh3;
        ((float*)(dynsm + SM_BIAS))[t] =
            bi[gate * HH + u0 + du] + bh[gate * HH + u0 + du];
    }
    if (t < 128) {
        #pragma unroll
        for (int i = 0; i < 24; i++) cbase[i * 128 + t] = 0.0f;
    }
    __syncthreads();
    if ((t & 31) == 0) {
        #pragma unroll
        for (int s = 0; s < NSTG; s++) mbar_arrive(smbase + MB_EMPTY + 8 * s);
    }
    __syncthreads();

    // ---- per-thread fragment byte offsets (relative to A/B region bases) ----
    const int lane = t & 31, wrp = t >> 5;
    const int mg = wrp & 3, kq = wrp >> 2;
    const int mat = lane >> 3, rr = lane & 7;
    uint32_t oa[2][2], ob[2][2];
    #pragma unroll
    for (int mf = 0; mf < 2; mf++) {
        int R  = mg * 32 + mf * 16 + ((mat & 1) << 3) + rr;
        int kg = kq * 2 + (mat >> 1);
        uint32_t base = (uint32_t)(R * 128 + ((kg ^ (R & 7)) << 4));
        oa[0][mf] = base;
        oa[1][mf] = base + 16384;
    }
    #pragma unroll
    for (int ntp = 0; ntp < 2; ntp++) {
        int nt = ntp * 2 + (mat >> 1);
        int kg = kq * 2 + (mat & 1);
        int n  = nt * 8 + rr;
        uint32_t base = (uint32_t)(n * 128 + ((kg ^ (n & 7)) << 4));
        ob[0][ntp] = base;
        ob[1][ntp] = base + 4096;
    }

    // ---- init: zero h/x/phases, pre-split seq, re-layout+split weights ----
    for (long e = gtid; e < 4 * TT + 8; e += gstr) g_ph[e] = 0;
    for (long e = gtid; e < HLAY; e += gstr) {
        #pragma unroll
        for (int l = 0; l < 3; l++) g_hA[l][0][e] = __ushort_as_half(0);
    }
    for (long e = gtid; e < 4 * HCH; e += gstr)
        g_xA[e] = __ushort_as_half(0);
    for (long n = gtid; n < (long)TT * 4 * HCH; n += gstr) {
        int tt = (int)(n / (4 * HCH));
        int r  = (int)(n % (4 * HCH));
        int ch = r / HCH; int r2 = r % HCH;
        int p  = r2 >> 13;
        int r3 = r2 & 8191;
        int b  = r3 >> 6;
        int pos = r3 & 63;
        int c  = ch * 64 + (((pos >> 3) ^ (b & 7)) << 3) + (pos & 7);
        float v = (c < CC) ? seq[((size_t)b * TT + tt) * CC + c] : 0.0f;
        __half h = __float2half_rn(v);
        g_seqA[tt][r] = p ? __float2half_rn(v - __half2float(h)) : h;
    }
    for (long n = gtid; n < 5L * NBLK * 16 * WCH; n += gstr) {
        int m   = (int)(n / ((long)NBLK * 16 * WCH));
        long r  = n % ((long)NBLK * 16 * WCH);
        int bl  = (int)(r / (16 * WCH));
        int r2  = (int)(r % (16 * WCH));
        int ch  = r2 / WCH;
        int r3  = r2 % WCH;
        int p   = r3 >> 11;
        int nl  = (r3 >> 6) & 31;
        int pos = r3 & 63;
        int kk  = (((pos >> 3) ^ (nl & 7)) << 3) + (pos & 7);
        int k   = ch * 64 + kk;
        int R   = (nl >> 3) * HH + bl * 8 + (nl & 7);
        const float* Wm = (m == 0) ? w_hh1 : (m == 1) ? w_ih2 :
                          (m == 2) ? w_hh2 : (m == 3) ? w_ih3 : w_hh3;
        float v = Wm[(size_t)R * HH + k];
        __half h = __float2half_rn(v);
        g_wb[0][0][n] = p ? __float2half_rn(v - __half2float(h)) : h;
    }
    for (long n = gtid; n < (long)NBLK * 4 * WCH; n += gstr) {
        int bl  = (int)(n / (4 * WCH));
        int r2  = (int)(n % (4 * WCH));
        int ch  = r2 / WCH;
        int r3  = r2 % WCH;
        int p   = r3 >> 11;
        int nl  = (r3 >> 6) & 31;
        int pos = r3 & 63;
        int kk  = (((pos >> 3) ^ (nl & 7)) << 3) + (pos & 7);
        int k   = ch * 64 + kk;
        int R   = (nl >> 3) * HH + bl * 8 + (nl & 7);
        float v = (k < CC) ? w_ih1[(size_t)R * CC + k] : 0.0f;
        __half h = __float2half_rn(v);
        g_w1b[0][n] = p ? __float2half_rn(v - __half2float(h)) : h;
    }
    grid_sync();

    const int gt   = *gtp;
    const int cond = *condp;
    int period = gt + cond;
    if (period < 1) period = 1;

    int gidx = 0;

    #pragma unroll 1
    for (int ts = 0; ts < TT; ts++) {
        const int rd = ts & 1, wr = rd ^ 1;
        const bool use_gt = (ts % period) < gt;
        const __half* X = use_gt ? g_seqA[ts] : g_xA;
        const int phb = ts * 4;

        float acc[2][4][4];

        // ---- Layer 1: hh (8 slots) then x (2 slots); chain -> L2 hh ----
        #pragma unroll
        for (int i = 0; i < 2; i++)
            #pragma unroll
            for (int j = 0; j < 4; j++)
                #pragma unroll
                for (int k = 0; k < 4; k++) acc[i][j][k] = 0.0f;
        gemm2(g_hA[0][rd], g_wb[0][blk], 8, X, g_w1b[blk], 2,
              (!use_gt && ts > 0) ? (phb - 1) : -1,
              g_hA[1][rd], g_wb[2][blk], -1, ts == 0,
              smbase, acc, oa, ob, gidx);
        layer_finish(acc, sbias + 0, cbase + 0, g_hA[0][wr], (float*)0,
                     scratch);
        if (t == 0) atomicAdd(&g_ph[phb + 0], 1);

        // ---- Layer 2: hh then ih; chain -> L3 hh ----
        #pragma unroll
        for (int i = 0; i < 2; i++)
            #pragma unroll
            for (int j = 0; j < 4; j++)
                #pragma unroll
                for (int k = 0; k < 4; k++) acc[i][j][k] = 0.0f;
        gemm2(g_hA[1][rd], g_wb[2][blk], 8, g_hA[0][wr], g_wb[1][blk], 8,
              phb + 0,
              g_hA[2][rd], g_wb[4][blk], -1, false,
              smbase, acc, oa, ob, gidx);
        layer_finish(acc, sbias + 32, cbase + 1024, g_hA[1][wr], (float*)0,
                     scratch);
        if (t == 0) atomicAdd(&g_ph[phb + 1], 1);

        // ---- Layer 3: hh then ih; chain -> next-step L1 hh (gate phb+0) ----
        #pragma unroll
        for (int i = 0; i < 2; i++)
            #pragma unroll
            for (int j = 0; j < 4; j++)
                #pragma unroll
                for (int k = 0; k < 4; k++) acc[i][j][k] = 0.0f;
        gemm2(g_hA[2][rd], g_wb[4][blk], 8, g_hA[1][wr], g_wb[3][blk], 8,
              phb + 1,
              (ts + 1 < TT) ? g_hA[0][wr] : (const __half*)0,
              g_wb[0][blk], phb + 0, false,
              smbase, acc, oa, ob, gidx);
        layer_finish(acc, sbias + 64, cbase + 2048, g_hA[2][wr], g_h3,
                     scratch);
        if (t == 0) atomicAdd(&g_ph[phb + 2], 1);

        // ---- Decoder (block-wide wait on L3 phase; arrives D phase) ----
        decoder_phase(g_h3, dec_w, dec_b, out + (size_t)ts * CC, sH,
                      phb + 2, phb + 3);
    }
}

// ---------------------------------------------------------------------------
extern "C" void kernel_launch(void* const* d_in, const int* in_sizes, int n_in,
                              void* d_out, int out_size)
{
    (void)in_sizes; (void)n_in; (void)out_size;
    cudaFuncSetAttribute(aclstm_kernel,
                         cudaFuncAttributeMaxDynamicSharedMemorySize,
                         SMEM_BYTES);
    aclstm_kernel<<<NBLK, NTHR, SMEM_BYTES>>>(
        (const float*)d_in[0],
        (const float*)d_in[1],  (const float*)d_in[2],
        (const float*)d_in[3],  (const float*)d_in[4],
        (const float*)d_in[5],  (const float*)d_in[6],
        (const float*)d_in[7],  (const float*)d_in[8],
        (const float*)d_in[9],  (const float*)d_in[10],
        (const float*)d_in[11], (const float*)d_in[12],
        (const float*)d_in[13], (const float*)d_in[14],
        (const int*)d_in[15],   (const int*)d_in[16],
        (float*)d_out);
}